// round 1
// baseline (speedup 1.0000x reference)
#include <cuda_runtime.h>
#include <math.h>

// Problem constants
#define DIMC     512
#define NQKV     1536
#define M_TOTAL  100352      // 8*256*49
#define SEQ      49
#define NWIN     2048        // 8*256
#define SCALEQ   0.17677669529663687f   // 32^-0.5 (HEAD_DIM=32)

// Scratch for qkv = x @ W + b  (616 MB, allowed as __device__ global)
__device__ float g_qkv[(size_t)M_TOTAL * NQKV];

// ---------------------------------------------------------------------------
// Kernel 1: qkv GEMM.  C[M=100352, N=1536] = x[M,512] @ W[512,1536] + bias
// SCALE folded into q columns (n < 512).
// 128x128 block tile, BK=8, 256 threads, 8x8 register tile per thread.
// All dims divide evenly (100352/128=784, 1536/128=12, 512/8=64): no guards.
// ---------------------------------------------------------------------------
__global__ __launch_bounds__(256, 2)
void qkv_gemm_kernel(const float* __restrict__ x,
                     const float* __restrict__ W,
                     const float* __restrict__ bias)
{
    const int BM = 128, BN = 128, BK = 8;
    __shared__ float As[BK][BM];   // A tile, transposed: As[k][m]
    __shared__ float Bs[BK][BN];   // B tile: Bs[k][n]

    const int bn0 = blockIdx.x * BN;
    const int bm0 = blockIdx.y * BM;
    const int tid = threadIdx.x;
    const int tx  = tid & 15;        // 0..15 -> n
    const int ty  = tid >> 4;        // 0..15 -> m

    // A-load mapping: each thread loads one float4 of the 128x8 tile
    const int a_row  = tid >> 1;            // 0..127
    const int a_col4 = (tid & 1) * 4;       // 0 or 4
    // B-load mapping: each thread loads one float4 of the 8x128 tile
    const int b_row  = tid >> 5;            // 0..7
    const int b_col4 = (tid & 31) * 4;      // 0..124

    const float* Aptr = x + (size_t)(bm0 + a_row) * DIMC + a_col4;
    const float* Bptr = W + (size_t)b_row * NQKV + bn0 + b_col4;

    float acc[8][8];
    #pragma unroll
    for (int i = 0; i < 8; i++)
        #pragma unroll
        for (int j = 0; j < 8; j++) acc[i][j] = 0.0f;

    for (int k0 = 0; k0 < DIMC; k0 += BK) {
        float4 av = *(const float4*)(Aptr + k0);
        float4 bv = *(const float4*)(Bptr + (size_t)k0 * NQKV);

        As[a_col4 + 0][a_row] = av.x;
        As[a_col4 + 1][a_row] = av.y;
        As[a_col4 + 2][a_row] = av.z;
        As[a_col4 + 3][a_row] = av.w;
        *(float4*)&Bs[b_row][b_col4] = bv;
        __syncthreads();

        #pragma unroll
        for (int k = 0; k < BK; k++) {
            float4 a0 = *(const float4*)&As[k][ty * 8];
            float4 a1 = *(const float4*)&As[k][ty * 8 + 4];
            float4 b0 = *(const float4*)&Bs[k][tx * 8];
            float4 b1 = *(const float4*)&Bs[k][tx * 8 + 4];
            float a[8] = {a0.x, a0.y, a0.z, a0.w, a1.x, a1.y, a1.z, a1.w};
            float b[8] = {b0.x, b0.y, b0.z, b0.w, b1.x, b1.y, b1.z, b1.w};
            #pragma unroll
            for (int i = 0; i < 8; i++)
                #pragma unroll
                for (int j = 0; j < 8; j++)
                    acc[i][j] = fmaf(a[i], b[j], acc[i][j]);
        }
        __syncthreads();
    }

    // Epilogue: add bias, scale q columns, store.
    // BN=128 and 512 % 128 == 0 -> the q/kv split is uniform per block.
    const float scale = (bn0 < DIMC) ? SCALEQ : 1.0f;
    #pragma unroll
    for (int i = 0; i < 8; i++) {
        const int m = bm0 + ty * 8 + i;
        float* crow = g_qkv + (size_t)m * NQKV + bn0 + tx * 8;
        #pragma unroll
        for (int j = 0; j < 8; j += 4) {
            const int n = bn0 + tx * 8 + j;
            float4 v;
            v.x = (acc[i][j + 0] + bias[n + 0]) * scale;
            v.y = (acc[i][j + 1] + bias[n + 1]) * scale;
            v.z = (acc[i][j + 2] + bias[n + 2]) * scale;
            v.w = (acc[i][j + 3] + bias[n + 3]) * scale;
            *(float4*)(crow + j) = v;
        }
    }
}

// ---------------------------------------------------------------------------
// Kernel 2: per-window attention. One CTA per window (2048 CTAs, 256 thr).
// smem layout (floats):
//   sQ : [512][52]  Q transposed, rows padded 49->52 (conflict-free float4)
//   sK : [512][52]  K transposed; reused for V after S is computed
//   sS : [52][52]   scores / probabilities
// ---------------------------------------------------------------------------
#define QK_STRIDE 52
#define SMEM_ATTN_FLOATS (2 * DIMC * QK_STRIDE + QK_STRIDE * QK_STRIDE)
#define SMEM_ATTN_BYTES  (SMEM_ATTN_FLOATS * 4)

__global__ __launch_bounds__(256, 1)
void attn_kernel(float* __restrict__ out)
{
    extern __shared__ float sm[];
    float* sQ = sm;                          // 512*52
    float* sK = sm + DIMC * QK_STRIDE;       // 512*52 (later V)
    float* sS = sm + 2 * DIMC * QK_STRIDE;   // 52*52

    const int w   = blockIdx.x;
    const int tid = threadIdx.x;
    const size_t base = (size_t)w * SEQ;

    // Load Q (pre-scaled) and K, transposed: s[c*52 + i]
    for (int idx = tid; idx < SEQ * DIMC; idx += 256) {
        const int i = idx >> 9;       // token 0..48
        const int c = idx & 511;      // channel
        const float* row = g_qkv + (base + i) * NQKV;
        sQ[c * QK_STRIDE + i] = row[c];
        sK[c * QK_STRIDE + i] = row[DIMC + c];
    }
    __syncthreads();

    // S = Q K^T over c. 13x13 active threads, each a 4x4 tile (52x52 cover).
    const int stx = tid % 16;
    const int sty = tid / 16;
    if (stx < 13 && sty < 13) {
        const int r0 = sty * 4;
        const int c0 = stx * 4;
        float accS[4][4];
        #pragma unroll
        for (int i = 0; i < 4; i++)
            #pragma unroll
            for (int j = 0; j < 4; j++) accS[i][j] = 0.0f;

        for (int c = 0; c < DIMC; c++) {
            float4 qa = *(const float4*)&sQ[c * QK_STRIDE + r0];
            float4 kb = *(const float4*)&sK[c * QK_STRIDE + c0];
            float qv[4] = {qa.x, qa.y, qa.z, qa.w};
            float kv[4] = {kb.x, kb.y, kb.z, kb.w};
            #pragma unroll
            for (int i = 0; i < 4; i++)
                #pragma unroll
                for (int j = 0; j < 4; j++)
                    accS[i][j] = fmaf(qv[i], kv[j], accS[i][j]);
        }
        #pragma unroll
        for (int i = 0; i < 4; i++) {
            float4 v = make_float4(accS[i][0], accS[i][1], accS[i][2], accS[i][3]);
            *(float4*)&sS[(r0 + i) * QK_STRIDE + c0] = v;
        }
    }
    __syncthreads();   // all reads of sK (as K) done

    // Load V into sK buffer (transposed), and zero the j=49..51 padding.
    for (int idx = tid; idx < SEQ * DIMC; idx += 256) {
        const int i = idx >> 9;
        const int c = idx & 511;
        sK[c * QK_STRIDE + i] = g_qkv[(base + i) * NQKV + 2 * DIMC + c];
    }
    for (int idx = tid; idx < DIMC * 3; idx += 256) {
        const int c = idx / 3;
        const int j = SEQ + (idx % 3);
        sK[c * QK_STRIDE + j] = 0.0f;
    }

    // Softmax per row (rows 0..48), and zero padding cols of sS.
    if (tid < SEQ) {
        float* row = sS + tid * QK_STRIDE;
        float mx = -1e30f;
        for (int j = 0; j < SEQ; j++) mx = fmaxf(mx, row[j]);
        float sum = 0.0f;
        for (int j = 0; j < SEQ; j++) {
            float e = __expf(row[j] - mx);
            row[j] = e;
            sum += e;
        }
        const float inv = 1.0f / sum;
        for (int j = 0; j < SEQ; j++) row[j] *= inv;
        row[49] = 0.0f; row[50] = 0.0f; row[51] = 0.0f;
    }
    __syncthreads();

    // out[i][c] = sum_j P[i][j] * V[j][c].  Each thread owns 2 channels,
    // 7-row register blocking to reuse V loads.
    const int ch0 = tid * 2;
    const float* Vt = sK;
    for (int i0 = 0; i0 < SEQ; i0 += 7) {
        float acc[7][2];
        #pragma unroll
        for (int ii = 0; ii < 7; ii++) { acc[ii][0] = 0.0f; acc[ii][1] = 0.0f; }

        #pragma unroll
        for (int j0 = 0; j0 < 52; j0 += 4) {
            float4 va = *(const float4*)&Vt[(ch0 + 0) * QK_STRIDE + j0];
            float4 vb = *(const float4*)&Vt[(ch0 + 1) * QK_STRIDE + j0];
            #pragma unroll
            for (int ii = 0; ii < 7; ii++) {
                float4 p = *(const float4*)&sS[(i0 + ii) * QK_STRIDE + j0];
                acc[ii][0] += p.x * va.x + p.y * va.y + p.z * va.z + p.w * va.w;
                acc[ii][1] += p.x * vb.x + p.y * vb.y + p.z * vb.z + p.w * vb.w;
            }
        }
        #pragma unroll
        for (int ii = 0; ii < 7; ii++) {
            float2 o = make_float2(acc[ii][0], acc[ii][1]);
            *(float2*)&out[(base + i0 + ii) * DIMC + ch0] = o;
        }
    }
}

// ---------------------------------------------------------------------------
extern "C" void kernel_launch(void* const* d_in, const int* in_sizes, int n_in,
                              void* d_out, int out_size)
{
    const float* x    = (const float*)d_in[0];
    // d_in[1] = x_all : unused by the reference
    const float* W    = (const float*)d_in[2];
    const float* bias = (const float*)d_in[3];
    float* out        = (float*)d_out;

    cudaFuncSetAttribute(attn_kernel,
                         cudaFuncAttributeMaxDynamicSharedMemorySize,
                         SMEM_ATTN_BYTES);

    dim3 gemm_grid(NQKV / 128, M_TOTAL / 128);   // 12 x 784
    qkv_gemm_kernel<<<gemm_grid, 256>>>(x, W, bias);

    attn_kernel<<<NWIN, 256, SMEM_ATTN_BYTES>>>(out);
}

// round 4
// speedup vs baseline: 1.8705x; 1.8705x over previous
#include <cuda_runtime.h>
#include <cuda_bf16.h>
#include <cstdint>
#include <math.h>

// Problem constants
#define DIMC     512
#define NQKV     1536
#define M_TOTAL  100352      // 8*256*49
#define SEQ      49
#define NWIN     2048        // 8*256
#define SCALEQ   0.17677669529663687f   // 32^-0.5
#define KPP      1536        // expanded K: [hi | lo | hi] x [hi | hi | lo]

// Scratch (__device__ globals: the sanctioned scratch mechanism)
__device__ float         g_qkv[(size_t)M_TOTAL * NQKV];   // 616 MB
__device__ __nv_bfloat16 g_A2 [(size_t)M_TOTAL * KPP];    // 308 MB
__device__ __nv_bfloat16 g_Wt2[(size_t)NQKV    * KPP];    // 4.7 MB  (N-major, K-contig)

// ---------------------------------------------------------------------------
// Helpers
// ---------------------------------------------------------------------------
__device__ __forceinline__ uint32_t smem_u32(const void* p) {
    uint32_t a;
    asm("{ .reg .u64 t; cvta.to.shared.u64 t, %1; cvt.u32.u64 %0, t; }" : "=r"(a) : "l"(p));
    return a;
}
__device__ __forceinline__ void cp16(uint32_t s, const void* g) {
    asm volatile("cp.async.cg.shared.global [%0], [%1], 16;" :: "r"(s), "l"(g));
}
__device__ __forceinline__ void ldsm4(uint32_t* r, uint32_t addr) {
    asm volatile("ldmatrix.sync.aligned.m8n8.x4.shared.b16 {%0,%1,%2,%3}, [%4];"
        : "=r"(r[0]), "=r"(r[1]), "=r"(r[2]), "=r"(r[3]) : "r"(addr));
}
__device__ __forceinline__ void mma16816(float* d, const uint32_t* a, uint32_t b0, uint32_t b1) {
    asm volatile("mma.sync.aligned.m16n8k16.row.col.f32.bf16.bf16.f32 "
        "{%0,%1,%2,%3}, {%4,%5,%6,%7}, {%8,%9}, {%0,%1,%2,%3};"
        : "+f"(d[0]), "+f"(d[1]), "+f"(d[2]), "+f"(d[3])
        : "r"(a[0]), "r"(a[1]), "r"(a[2]), "r"(a[3]), "r"(b0), "r"(b1));
}
__device__ __forceinline__ uint32_t pack_bf16(__nv_bfloat16 a, __nv_bfloat16 b) {
    return (uint32_t)__bfloat16_as_ushort(a) | ((uint32_t)__bfloat16_as_ushort(b) << 16);
}

// ---------------------------------------------------------------------------
// Conversion: x (fp32) -> g_A2 = [hi | lo | hi] bf16 along K''
// ---------------------------------------------------------------------------
__global__ __launch_bounds__(256)
void convert_x_kernel(const float* __restrict__ x)
{
    size_t i4 = (size_t)blockIdx.x * 256 + threadIdx.x;   // 100352*128 float4s
    float4 v = reinterpret_cast<const float4*>(x)[i4];
    size_t m = i4 >> 7;
    int kq   = (int)(i4 & 127);

    __nv_bfloat16 h0 = __float2bfloat16(v.x), h1 = __float2bfloat16(v.y);
    __nv_bfloat16 h2 = __float2bfloat16(v.z), h3 = __float2bfloat16(v.w);
    __nv_bfloat16 l0 = __float2bfloat16(v.x - __bfloat162float(h0));
    __nv_bfloat16 l1 = __float2bfloat16(v.y - __bfloat162float(h1));
    __nv_bfloat16 l2 = __float2bfloat16(v.z - __bfloat162float(h2));
    __nv_bfloat16 l3 = __float2bfloat16(v.w - __bfloat162float(h3));

    uint2 uh, ul;
    uh.x = pack_bf16(h0, h1); uh.y = pack_bf16(h2, h3);
    ul.x = pack_bf16(l0, l1); ul.y = pack_bf16(l2, l3);

    __nv_bfloat16* dst = g_A2 + m * KPP + kq * 4;
    *reinterpret_cast<uint2*>(dst)        = uh;   // hi  at k
    *reinterpret_cast<uint2*>(dst + 512)  = ul;   // lo  at k+512
    *reinterpret_cast<uint2*>(dst + 1024) = uh;   // hi  at k+1024
}

// W[k][n] -> g_Wt2[n][ hi(k) | hi(k) | lo(k) ]
__global__ __launch_bounds__(256)
void convert_W_kernel(const float* __restrict__ W)
{
    int idx = blockIdx.x * 256 + threadIdx.x;   // 512*1536
    int k = idx / NQKV;
    int n = idx % NQKV;
    float v = W[idx];
    __nv_bfloat16 hi = __float2bfloat16(v);
    __nv_bfloat16 lo = __float2bfloat16(v - __bfloat162float(hi));
    __nv_bfloat16* row = g_Wt2 + (size_t)n * KPP;
    row[k]        = hi;
    row[512 + k]  = hi;
    row[1024 + k] = lo;
}

// ---------------------------------------------------------------------------
// HMMA GEMM: g_qkv[M,1536] = A2[M,K''] x Wt2[N,K'']^T + bias (q cols scaled)
// CTA tile 128x128, BK=32, 8 warps (warp tile 32x64), cp.async double buffer.
// smem rows are 80 B pitch (64 B data + 16 pad): rows 0..7 start at banks
// {0,20,8,28,16,4,24,12} -> ldmatrix / STS conflict-free without swizzle.
// ---------------------------------------------------------------------------
#define ROWB         80
#define TILE_BYTES   (128 * ROWB)            // 10240 per operand
#define STAGE_BYTES  (2 * TILE_BYTES)        // A + B
#define NCHUNK       (KPP / 32)              // 48

__global__ __launch_bounds__(256, 2)
void qkv_gemm_mma(const float* __restrict__ bias)
{
    __shared__ char sbuf[2 * STAGE_BYTES];   // 40960 B
    const uint32_t sbase = smem_u32(sbuf);

    const int tid  = threadIdx.x;
    const int wid  = tid >> 5;
    const int lane = tid & 31;
    const int wm   = wid >> 1;               // 0..3 -> M offset wm*32
    const int wn   = wid & 1;                // 0..1 -> N offset wn*64
    const int bn0  = blockIdx.x * 128;
    const int bm0  = blockIdx.y * 128;

    // cp.async geometry: 2 chunks per operand per thread
    const int rc = tid >> 2;                 // 0..63
    const int jc = tid & 3;                  // 0..3
    const __nv_bfloat16* Ag = g_A2  + (size_t)(bm0 + rc) * KPP + jc * 8;
    const __nv_bfloat16* Bg = g_Wt2 + (size_t)(bn0 + rc) * KPP + jc * 8;
    const uint32_t sA_off = (uint32_t)(rc * ROWB + jc * 16);

    float acc[2][8][4];
    #pragma unroll
    for (int mi = 0; mi < 2; mi++)
        #pragma unroll
        for (int ni = 0; ni < 8; ni++)
            #pragma unroll
            for (int t = 0; t < 4; t++) acc[mi][ni][t] = 0.0f;

    // ldmatrix lane addressing (same formula for A and B)
    const uint32_t lrow = (uint32_t)(lane & 15);
    const uint32_t lcol = (uint32_t)((lane & 16) ? 16 : 0);

    // ---- prologue: issue chunk 0
    {
        const uint32_t st = sbase;
        cp16(st + sA_off,                      Ag);
        cp16(st + sA_off + 64 * ROWB,          Ag + (size_t)64 * KPP);
        cp16(st + TILE_BYTES + sA_off,         Bg);
        cp16(st + TILE_BYTES + sA_off + 64 * ROWB, Bg + (size_t)64 * KPP);
        asm volatile("cp.async.commit_group;" ::: "memory");
    }

    for (int c = 0; c < NCHUNK; ++c) {
        if (c + 1 < NCHUNK) {
            const int k0 = (c + 1) * 32;
            const uint32_t st = sbase + ((c + 1) & 1) * STAGE_BYTES;
            cp16(st + sA_off,                      Ag + k0);
            cp16(st + sA_off + 64 * ROWB,          Ag + (size_t)64 * KPP + k0);
            cp16(st + TILE_BYTES + sA_off,         Bg + k0);
            cp16(st + TILE_BYTES + sA_off + 64 * ROWB, Bg + (size_t)64 * KPP + k0);
            asm volatile("cp.async.commit_group;" ::: "memory");
            asm volatile("cp.async.wait_group 1;" ::: "memory");
        } else {
            asm volatile("cp.async.wait_group 0;" ::: "memory");
        }
        __syncthreads();

        const uint32_t sAu = sbase + (c & 1) * STAGE_BYTES;
        const uint32_t sBu = sAu + TILE_BYTES;
        const uint32_t aBase = sAu + (wm * 32 + lrow) * ROWB + lcol;
        const uint32_t bBase = sBu + (wn * 64 + lrow) * ROWB + lcol;

        #pragma unroll
        for (int ks = 0; ks < 2; ks++) {
            uint32_t afr[2][4];
            ldsm4(afr[0], aBase + ks * 32);
            ldsm4(afr[1], aBase + 16 * ROWB + ks * 32);
            #pragma unroll
            for (int pi = 0; pi < 4; pi++) {
                uint32_t bfr[4];
                ldsm4(bfr, bBase + pi * 16 * ROWB + ks * 32);
                mma16816(acc[0][2 * pi + 0], afr[0], bfr[0], bfr[2]);
                mma16816(acc[0][2 * pi + 1], afr[0], bfr[1], bfr[3]);
                mma16816(acc[1][2 * pi + 0], afr[1], bfr[0], bfr[2]);
                mma16816(acc[1][2 * pi + 1], afr[1], bfr[1], bfr[3]);
            }
        }
        __syncthreads();
    }

    // ---- epilogue: bias + scale, store fp32
    const float scale = (bn0 < DIMC) ? SCALEQ : 1.0f;
    const int r0 = bm0 + wm * 32 + (lane >> 2);
    const int c0 = bn0 + wn * 64 + (lane & 3) * 2;
    #pragma unroll
    for (int ni = 0; ni < 8; ni++) {
        const int col = c0 + ni * 8;
        const float2 bb = *reinterpret_cast<const float2*>(&bias[col]);
        #pragma unroll
        for (int mi = 0; mi < 2; mi++) {
            const int row = r0 + mi * 16;
            float2 v0, v1;
            v0.x = (acc[mi][ni][0] + bb.x) * scale;
            v0.y = (acc[mi][ni][1] + bb.y) * scale;
            v1.x = (acc[mi][ni][2] + bb.x) * scale;
            v1.y = (acc[mi][ni][3] + bb.y) * scale;
            *reinterpret_cast<float2*>(&g_qkv[(size_t)row * NQKV + col])       = v0;
            *reinterpret_cast<float2*>(&g_qkv[(size_t)(row + 8) * NQKV + col]) = v1;
        }
    }
}

// ---------------------------------------------------------------------------
// Kernel 2: per-window attention (unchanged from R1)
// ---------------------------------------------------------------------------
#define QK_STRIDE 52
#define SMEM_ATTN_FLOATS (2 * DIMC * QK_STRIDE + QK_STRIDE * QK_STRIDE)
#define SMEM_ATTN_BYTES  (SMEM_ATTN_FLOATS * 4)

__global__ __launch_bounds__(256, 1)
void attn_kernel(float* __restrict__ out)
{
    extern __shared__ float sm[];
    float* sQ = sm;
    float* sK = sm + DIMC * QK_STRIDE;
    float* sS = sm + 2 * DIMC * QK_STRIDE;

    const int w   = blockIdx.x;
    const int tid = threadIdx.x;
    const size_t base = (size_t)w * SEQ;

    for (int idx = tid; idx < SEQ * DIMC; idx += 256) {
        const int i = idx >> 9;
        const int c = idx & 511;
        const float* row = g_qkv + (base + i) * NQKV;
        sQ[c * QK_STRIDE + i] = row[c];
        sK[c * QK_STRIDE + i] = row[DIMC + c];
    }
    __syncthreads();

    const int stx = tid % 16;
    const int sty = tid / 16;
    if (stx < 13 && sty < 13) {
        const int r0 = sty * 4;
        const int c0 = stx * 4;
        float accS[4][4];
        #pragma unroll
        for (int i = 0; i < 4; i++)
            #pragma unroll
            for (int j = 0; j < 4; j++) accS[i][j] = 0.0f;

        for (int c = 0; c < DIMC; c++) {
            float4 qa = *(const float4*)&sQ[c * QK_STRIDE + r0];
            float4 kb = *(const float4*)&sK[c * QK_STRIDE + c0];
            float qv[4] = {qa.x, qa.y, qa.z, qa.w};
            float kv[4] = {kb.x, kb.y, kb.z, kb.w};
            #pragma unroll
            for (int i = 0; i < 4; i++)
                #pragma unroll
                for (int j = 0; j < 4; j++)
                    accS[i][j] = fmaf(qv[i], kv[j], accS[i][j]);
        }
        #pragma unroll
        for (int i = 0; i < 4; i++) {
            float4 v = make_float4(accS[i][0], accS[i][1], accS[i][2], accS[i][3]);
            *(float4*)&sS[(r0 + i) * QK_STRIDE + c0] = v;
        }
    }
    __syncthreads();

    for (int idx = tid; idx < SEQ * DIMC; idx += 256) {
        const int i = idx >> 9;
        const int c = idx & 511;
        sK[c * QK_STRIDE + i] = g_qkv[(base + i) * NQKV + 2 * DIMC + c];
    }
    for (int idx = tid; idx < DIMC * 3; idx += 256) {
        const int c = idx / 3;
        const int j = SEQ + (idx % 3);
        sK[c * QK_STRIDE + j] = 0.0f;
    }

    if (tid < SEQ) {
        float* row = sS + tid * QK_STRIDE;
        float mx = -1e30f;
        for (int j = 0; j < SEQ; j++) mx = fmaxf(mx, row[j]);
        float sum = 0.0f;
        for (int j = 0; j < SEQ; j++) {
            float e = __expf(row[j] - mx);
            row[j] = e;
            sum += e;
        }
        const float inv = 1.0f / sum;
        for (int j = 0; j < SEQ; j++) row[j] *= inv;
        row[49] = 0.0f; row[50] = 0.0f; row[51] = 0.0f;
    }
    __syncthreads();

    const int ch0 = tid * 2;
    const float* Vt = sK;
    for (int i0 = 0; i0 < SEQ; i0 += 7) {
        float acc[7][2];
        #pragma unroll
        for (int ii = 0; ii < 7; ii++) { acc[ii][0] = 0.0f; acc[ii][1] = 0.0f; }

        #pragma unroll
        for (int j0 = 0; j0 < 52; j0 += 4) {
            float4 va = *(const float4*)&Vt[(ch0 + 0) * QK_STRIDE + j0];
            float4 vb = *(const float4*)&Vt[(ch0 + 1) * QK_STRIDE + j0];
            #pragma unroll
            for (int ii = 0; ii < 7; ii++) {
                float4 p = *(const float4*)&sS[(i0 + ii) * QK_STRIDE + j0];
                acc[ii][0] += p.x * va.x + p.y * va.y + p.z * va.z + p.w * va.w;
                acc[ii][1] += p.x * vb.x + p.y * vb.y + p.z * vb.z + p.w * vb.w;
            }
        }
        #pragma unroll
        for (int ii = 0; ii < 7; ii++) {
            float2 o = make_float2(acc[ii][0], acc[ii][1]);
            *(float2*)&out[(base + i0 + ii) * DIMC + ch0] = o;
        }
    }
}

// ---------------------------------------------------------------------------
extern "C" void kernel_launch(void* const* d_in, const int* in_sizes, int n_in,
                              void* d_out, int out_size)
{
    const float* x    = (const float*)d_in[0];
    // d_in[1] = x_all : unused by the reference
    const float* W    = (const float*)d_in[2];
    const float* bias = (const float*)d_in[3];
    float* out        = (float*)d_out;

    cudaFuncSetAttribute(attn_kernel,
                         cudaFuncAttributeMaxDynamicSharedMemorySize,
                         SMEM_ATTN_BYTES);

    convert_x_kernel<<<(M_TOTAL * (DIMC / 4)) / 256, 256>>>(x);   // 50176 blocks
    convert_W_kernel<<<(DIMC * NQKV) / 256, 256>>>(W);            // 3072 blocks

    dim3 gemm_grid(NQKV / 128, M_TOTAL / 128);                    // 12 x 784
    qkv_gemm_mma<<<gemm_grid, 256>>>(bias);

    attn_kernel<<<NWIN, 256, SMEM_ATTN_BYTES>>>(out);
}

// round 6
// speedup vs baseline: 2.0466x; 1.0941x over previous
#include <cuda_runtime.h>
#include <cuda_bf16.h>
#include <cstdint>
#include <math.h>

// Problem constants
#define DIMC     512
#define NQKV     1536
#define M_TOTAL  100352      // 8*256*49
#define SEQ      49
#define NWIN     2048        // 8*256
#define SCALEQ   0.17677669529663687f   // 32^-0.5
#define KPP      1536        // expanded K: [hi | lo | hi] x [hi | hi | lo]

// Scratch (__device__ globals: the sanctioned scratch mechanism)
__device__ float         g_qkv[(size_t)M_TOTAL * NQKV];   // 616 MB
__device__ __nv_bfloat16 g_A2 [(size_t)M_TOTAL * KPP];    // 308 MB
__device__ __nv_bfloat16 g_Wt2[(size_t)NQKV    * KPP];    // 4.7 MB  (N-major, K-contig)

// ---------------------------------------------------------------------------
// Helpers
// ---------------------------------------------------------------------------
__device__ __forceinline__ uint32_t smem_u32(const void* p) {
    uint32_t a;
    asm("{ .reg .u64 t; cvta.to.shared.u64 t, %1; cvt.u32.u64 %0, t; }" : "=r"(a) : "l"(p));
    return a;
}
__device__ __forceinline__ void cp16(uint32_t s, const void* g) {
    asm volatile("cp.async.cg.shared.global [%0], [%1], 16;" :: "r"(s), "l"(g));
}
__device__ __forceinline__ void ldsm4(uint32_t* r, uint32_t addr) {
    asm volatile("ldmatrix.sync.aligned.m8n8.x4.shared.b16 {%0,%1,%2,%3}, [%4];"
        : "=r"(r[0]), "=r"(r[1]), "=r"(r[2]), "=r"(r[3]) : "r"(addr));
}
__device__ __forceinline__ void mma16816(float* d, const uint32_t* a, uint32_t b0, uint32_t b1) {
    asm volatile("mma.sync.aligned.m16n8k16.row.col.f32.bf16.bf16.f32 "
        "{%0,%1,%2,%3}, {%4,%5,%6,%7}, {%8,%9}, {%0,%1,%2,%3};"
        : "+f"(d[0]), "+f"(d[1]), "+f"(d[2]), "+f"(d[3])
        : "r"(a[0]), "r"(a[1]), "r"(a[2]), "r"(a[3]), "r"(b0), "r"(b1));
}
__device__ __forceinline__ uint32_t pack_bf16(__nv_bfloat16 a, __nv_bfloat16 b) {
    return (uint32_t)__bfloat16_as_ushort(a) | ((uint32_t)__bfloat16_as_ushort(b) << 16);
}

// ---------------------------------------------------------------------------
// Conversion: x (fp32) -> g_A2 = [hi | lo | hi] bf16 along K''
// ---------------------------------------------------------------------------
__global__ __launch_bounds__(256)
void convert_x_kernel(const float* __restrict__ x)
{
    size_t i4 = (size_t)blockIdx.x * 256 + threadIdx.x;   // 100352*128 float4s
    float4 v = reinterpret_cast<const float4*>(x)[i4];
    size_t m = i4 >> 7;
    int kq   = (int)(i4 & 127);

    __nv_bfloat16 h0 = __float2bfloat16(v.x), h1 = __float2bfloat16(v.y);
    __nv_bfloat16 h2 = __float2bfloat16(v.z), h3 = __float2bfloat16(v.w);
    __nv_bfloat16 l0 = __float2bfloat16(v.x - __bfloat162float(h0));
    __nv_bfloat16 l1 = __float2bfloat16(v.y - __bfloat162float(h1));
    __nv_bfloat16 l2 = __float2bfloat16(v.z - __bfloat162float(h2));
    __nv_bfloat16 l3 = __float2bfloat16(v.w - __bfloat162float(h3));

    uint2 uh, ul;
    uh.x = pack_bf16(h0, h1); uh.y = pack_bf16(h2, h3);
    ul.x = pack_bf16(l0, l1); ul.y = pack_bf16(l2, l3);

    __nv_bfloat16* dst = g_A2 + m * KPP + kq * 4;
    *reinterpret_cast<uint2*>(dst)        = uh;   // hi  at k
    *reinterpret_cast<uint2*>(dst + 512)  = ul;   // lo  at k+512
    *reinterpret_cast<uint2*>(dst + 1024) = uh;   // hi  at k+1024
}

// W[k][n] -> g_Wt2[n][ hi(k) | hi(k) | lo(k) ]
__global__ __launch_bounds__(256)
void convert_W_kernel(const float* __restrict__ W)
{
    int idx = blockIdx.x * 256 + threadIdx.x;   // 512*1536
    int k = idx / NQKV;
    int n = idx % NQKV;
    float v = W[idx];
    __nv_bfloat16 hi = __float2bfloat16(v);
    __nv_bfloat16 lo = __float2bfloat16(v - __bfloat162float(hi));
    __nv_bfloat16* row = g_Wt2 + (size_t)n * KPP;
    row[k]        = hi;
    row[512 + k]  = hi;
    row[1024 + k] = lo;
}

// ---------------------------------------------------------------------------
// HMMA GEMM: g_qkv[M,1536] = A2[M,K''] x Wt2[N,K'']^T + bias (q cols scaled)
// CTA tile 128x128, BK=32, 8 warps (warp tile 32x64), 3-stage cp.async
// pipeline with ONE __syncthreads per K-chunk.
// smem rows 80 B pitch: rows 0..7 start at banks {0,20,8,28,16,4,24,12}
// -> ldmatrix / STS conflict-free without swizzle.
// ---------------------------------------------------------------------------
#define ROWB         80
#define TILE_BYTES   (128 * ROWB)            // 10240 per operand
#define STAGE_BYTES  (2 * TILE_BYTES)        // A + B = 20480
#define GEMM_SMEM    (3 * STAGE_BYTES)       // 61440
#define NCHUNK       (KPP / 32)              // 48

__global__ __launch_bounds__(256, 2)
void qkv_gemm_mma(const float* __restrict__ bias)
{
    extern __shared__ char sbuf[];
    const uint32_t sbase = smem_u32(sbuf);

    const int tid  = threadIdx.x;
    const int wid  = tid >> 5;
    const int lane = tid & 31;
    const int wm   = wid >> 1;               // 0..3 -> M offset wm*32
    const int wn   = wid & 1;                // 0..1 -> N offset wn*64
    const int bn0  = blockIdx.x * 128;
    const int bm0  = blockIdx.y * 128;

    // cp.async geometry
    const int rc = tid >> 2;                 // 0..63
    const int jc = tid & 3;                  // 0..3
    const __nv_bfloat16* Ag = g_A2  + (size_t)(bm0 + rc) * KPP + jc * 8;
    const __nv_bfloat16* Bg = g_Wt2 + (size_t)(bn0 + rc) * KPP + jc * 8;
    const uint32_t sA_off = (uint32_t)(rc * ROWB + jc * 16);

    float acc[2][8][4];
    #pragma unroll
    for (int mi = 0; mi < 2; mi++)
        #pragma unroll
        for (int ni = 0; ni < 8; ni++)
            #pragma unroll
            for (int t = 0; t < 4; t++) acc[mi][ni][t] = 0.0f;

    const uint32_t lrow = (uint32_t)(lane & 15);
    const uint32_t lcol = (uint32_t)((lane & 16) ? 16 : 0);

    #define ISSUE_STAGE(cc) do {                                             \
        const int _k0 = (cc) * 32;                                           \
        const uint32_t _st = sbase + ((cc) % 3) * STAGE_BYTES;               \
        cp16(_st + sA_off,                          Ag + _k0);               \
        cp16(_st + sA_off + 64 * ROWB,              Ag + (size_t)64 * KPP + _k0); \
        cp16(_st + TILE_BYTES + sA_off,             Bg + _k0);               \
        cp16(_st + TILE_BYTES + sA_off + 64 * ROWB, Bg + (size_t)64 * KPP + _k0); \
        asm volatile("cp.async.commit_group;" ::: "memory");                 \
    } while (0)

    ISSUE_STAGE(0);
    ISSUE_STAGE(1);

    for (int c = 0; c < NCHUNK; ++c) {
        if (c + 2 < NCHUNK) {
            asm volatile("cp.async.wait_group 1;" ::: "memory");
        } else {
            asm volatile("cp.async.wait_group 0;" ::: "memory");
        }
        __syncthreads();
        if (c + 2 < NCHUNK) ISSUE_STAGE(c + 2);

        const uint32_t sAu = sbase + (c % 3) * STAGE_BYTES;
        const uint32_t sBu = sAu + TILE_BYTES;
        const uint32_t aBase = sAu + (wm * 32 + lrow) * ROWB + lcol;
        const uint32_t bBase = sBu + (wn * 64 + lrow) * ROWB + lcol;

        #pragma unroll
        for (int ks = 0; ks < 2; ks++) {
            uint32_t afr[2][4];
            ldsm4(afr[0], aBase + ks * 32);
            ldsm4(afr[1], aBase + 16 * ROWB + ks * 32);
            #pragma unroll
            for (int pi = 0; pi < 4; pi++) {
                uint32_t bfr[4];
                ldsm4(bfr, bBase + pi * 16 * ROWB + ks * 32);
                mma16816(acc[0][2 * pi + 0], afr[0], bfr[0], bfr[2]);
                mma16816(acc[0][2 * pi + 1], afr[0], bfr[1], bfr[3]);
                mma16816(acc[1][2 * pi + 0], afr[1], bfr[0], bfr[2]);
                mma16816(acc[1][2 * pi + 1], afr[1], bfr[1], bfr[3]);
            }
        }
    }
    #undef ISSUE_STAGE

    // ---- epilogue: bias + scale, store fp32
    const float scale = (bn0 < DIMC) ? SCALEQ : 1.0f;
    const int r0 = bm0 + wm * 32 + (lane >> 2);
    const int c0 = bn0 + wn * 64 + (lane & 3) * 2;
    #pragma unroll
    for (int ni = 0; ni < 8; ni++) {
        const int col = c0 + ni * 8;
        const float2 bb = *reinterpret_cast<const float2*>(&bias[col]);
        #pragma unroll
        for (int mi = 0; mi < 2; mi++) {
            const int row = r0 + mi * 16;
            float2 v0, v1;
            v0.x = (acc[mi][ni][0] + bb.x) * scale;
            v0.y = (acc[mi][ni][1] + bb.y) * scale;
            v1.x = (acc[mi][ni][2] + bb.x) * scale;
            v1.y = (acc[mi][ni][3] + bb.y) * scale;
            *reinterpret_cast<float2*>(&g_qkv[(size_t)row * NQKV + col])       = v0;
            *reinterpret_cast<float2*>(&g_qkv[(size_t)(row + 8) * NQKV + col]) = v1;
        }
    }
}

// ---------------------------------------------------------------------------
// Kernel 2: per-window attention, C-chunked for occupancy 3.
//   Phase S : 4 chunks of 128 channels; sQ/sK transposed [c][i], stride 60.
//             S tiled 14x14 threads x (4x4) covering 56x56 (pads zeroed).
//   Softmax : warp-parallel, shfl reductions.
//   Phase PV: V staged naturally [j][c] (stride 132), P read as float4
//             broadcast, 5-row register blocking, 25/24 row split by tid>>7.
// ---------------------------------------------------------------------------
#define AST 56    // padded S dim
#define QST 60    // Q/K chunk row stride (floats)
#define VST 132   // V row stride (floats)
#define ATTN_SMEM_BYTES ((2 * 128 * QST + AST * AST) * 4)   // 73984

__global__ __launch_bounds__(256, 3)
void attn_kernel(float* __restrict__ out)
{
    extern __shared__ float sm[];
    float* sQ = sm;                       // 128*60
    float* sK = sm + 128 * QST;           // 128*60
    float* sS = sm + 2 * 128 * QST;       // 56*56
    float* sV = sm;                       // overlay on sQ/sK (56*132 <= 2*128*60)

    const int w   = blockIdx.x;
    const int tid = threadIdx.x;
    const size_t base = (size_t)w * SEQ;

    const int stx = tid & 15;
    const int sty = tid >> 4;
    const bool sact = (stx < 14) && (sty < 14);

    float accS[4][4];
    #pragma unroll
    for (int i = 0; i < 4; i++)
        #pragma unroll
        for (int j = 0; j < 4; j++) accS[i][j] = 0.0f;

    // ---- Phase S: accumulate over 4 channel chunks
    for (int ch = 0; ch < 4; ch++) {
        __syncthreads();   // protect sQ/sK reuse
        for (int idx = tid; idx < SEQ * 128; idx += 256) {
            const int i = idx >> 7;
            const int c = idx & 127;
            const float* row = g_qkv + (base + i) * NQKV + ch * 128 + c;
            sQ[c * QST + i] = row[0];
            sK[c * QST + i] = row[DIMC];
        }
        for (int idx = tid; idx < 7 * 128; idx += 256) {
            const int c = idx & 127;
            const int p = idx >> 7;
            sQ[c * QST + SEQ + p] = 0.0f;
            sK[c * QST + SEQ + p] = 0.0f;
        }
        __syncthreads();

        if (sact) {
            const float* qp = sQ + sty * 4;
            const float* kp = sK + stx * 4;
            for (int c = 0; c < 128; c++) {
                float4 qa = *(const float4*)(qp + c * QST);
                float4 kb = *(const float4*)(kp + c * QST);
                float qv[4] = {qa.x, qa.y, qa.z, qa.w};
                float kv[4] = {kb.x, kb.y, kb.z, kb.w};
                #pragma unroll
                for (int i = 0; i < 4; i++)
                    #pragma unroll
                    for (int j = 0; j < 4; j++)
                        accS[i][j] = fmaf(qv[i], kv[j], accS[i][j]);
            }
        }
    }

    // store S
    if (sact) {
        #pragma unroll
        for (int i = 0; i < 4; i++) {
            float4 v = make_float4(accS[i][0], accS[i][1], accS[i][2], accS[i][3]);
            *(float4*)&sS[(sty * 4 + i) * AST + stx * 4] = v;
        }
    }
    __syncthreads();

    // ---- Softmax: warp per row (rows wid, wid+8, ...)
    const int wid  = tid >> 5;
    const int lane = tid & 31;
    for (int r = wid; r < SEQ; r += 8) {
        float* row = sS + r * AST;
        const float v0 = (lane < SEQ)      ? row[lane]      : -1e30f;
        const float v1 = (lane + 32 < SEQ) ? row[lane + 32] : -1e30f;
        float mx = fmaxf(v0, v1);
        #pragma unroll
        for (int o = 16; o > 0; o >>= 1)
            mx = fmaxf(mx, __shfl_xor_sync(0xFFFFFFFFu, mx, o));
        const float e0 = (lane < SEQ)      ? __expf(v0 - mx) : 0.0f;
        const float e1 = (lane + 32 < SEQ) ? __expf(v1 - mx) : 0.0f;
        float s = e0 + e1;
        #pragma unroll
        for (int o = 16; o > 0; o >>= 1)
            s += __shfl_xor_sync(0xFFFFFFFFu, s, o);
        const float inv = 1.0f / s;
        if (lane < SEQ)      row[lane]      = e0 * inv;
        if (lane + 32 < AST) row[lane + 32] = e1 * inv;   // pads 49..55 -> 0
    }

    // ---- Phase PV over 4 channel chunks
    const int cl = tid & 127;   // channel within chunk
    const int hf = tid >> 7;    // 0: rows 0..24, 1: rows 25..48
    const int rb = hf * 25;
    const int nr = hf ? 24 : 25;

    for (int ch = 0; ch < 4; ch++) {
        __syncthreads();   // protect sV reuse (and sS after softmax on ch=0)
        for (int idx = tid; idx < SEQ * 128; idx += 256) {
            const int i = idx >> 7;
            const int c = idx & 127;
            sV[i * VST + c] = g_qkv[(base + i) * NQKV + 2 * DIMC + ch * 128 + c];
        }
        for (int idx = tid; idx < 7 * 128; idx += 256) {
            const int c = idx & 127;
            const int p = idx >> 7;
            sV[(SEQ + p) * VST + c] = 0.0f;
        }
        __syncthreads();

        #pragma unroll
        for (int g = 0; g < 5; g++) {
            const int r0 = rb + g * 5;
            float acc[5] = {0.0f, 0.0f, 0.0f, 0.0f, 0.0f};
            for (int j4 = 0; j4 < AST; j4 += 4) {
                const float va = sV[(j4 + 0) * VST + cl];
                const float vb = sV[(j4 + 1) * VST + cl];
                const float vc = sV[(j4 + 2) * VST + cl];
                const float vd = sV[(j4 + 3) * VST + cl];
                #pragma unroll
                for (int rr = 0; rr < 5; rr++) {
                    float4 p = *(const float4*)&sS[(r0 + rr) * AST + j4];
                    acc[rr] += p.x * va + p.y * vb + p.z * vc + p.w * vd;
                }
            }
            const int lim = nr - g * 5;   // 5 except last group of hf=1 -> 4
            #pragma unroll
            for (int rr = 0; rr < 5; rr++) {
                if (rr < lim)
                    out[(base + r0 + rr) * DIMC + ch * 128 + cl] = acc[rr];
            }
        }
    }
}

// ---------------------------------------------------------------------------
extern "C" void kernel_launch(void* const* d_in, const int* in_sizes, int n_in,
                              void* d_out, int out_size)
{
    const float* x    = (const float*)d_in[0];
    // d_in[1] = x_all : unused by the reference
    const float* W    = (const float*)d_in[2];
    const float* bias = (const float*)d_in[3];
    float* out        = (float*)d_out;

    cudaFuncSetAttribute(qkv_gemm_mma,
                         cudaFuncAttributeMaxDynamicSharedMemorySize, GEMM_SMEM);
    cudaFuncSetAttribute(attn_kernel,
                         cudaFuncAttributeMaxDynamicSharedMemorySize, ATTN_SMEM_BYTES);

    convert_x_kernel<<<(M_TOTAL * (DIMC / 4)) / 256, 256>>>(x);   // 50176 blocks
    convert_W_kernel<<<(DIMC * NQKV) / 256, 256>>>(W);            // 3072 blocks

    dim3 gemm_grid(NQKV / 128, M_TOTAL / 128);                    // 12 x 784
    qkv_gemm_mma<<<gemm_grid, 256, GEMM_SMEM>>>(bias);

    attn_kernel<<<NWIN, 256, ATTN_SMEM_BYTES>>>(out);
}

// round 7
// speedup vs baseline: 4.1718x; 2.0384x over previous
#include <cuda_runtime.h>
#include <cuda_fp16.h>
#include <cstdint>
#include <math.h>

// Problem constants
#define DIMC     512
#define NQKV     1536
#define M_TOTAL  100352      // 8*256*49
#define SEQ      49
#define NWIN     2048        // 8*256
#define SCALEQ   0.17677669529663687f   // 32^-0.5

// Scratch (__device__ globals: the sanctioned scratch mechanism)
__device__ float  g_qkv[(size_t)M_TOTAL * NQKV];   // 616 MB
__device__ __half g_Ah [(size_t)M_TOTAL * DIMC];   // 103 MB (fp16 x)
__device__ __half g_Wh [(size_t)NQKV    * DIMC];   // 1.6 MB (N-major, K-contig)

// ---------------------------------------------------------------------------
// Helpers
// ---------------------------------------------------------------------------
__device__ __forceinline__ uint32_t smem_u32(const void* p) {
    uint32_t a;
    asm("{ .reg .u64 t; cvta.to.shared.u64 t, %1; cvt.u32.u64 %0, t; }" : "=r"(a) : "l"(p));
    return a;
}
__device__ __forceinline__ void cp16(uint32_t s, const void* g) {
    asm volatile("cp.async.cg.shared.global [%0], [%1], 16;" :: "r"(s), "l"(g));
}
__device__ __forceinline__ void ldsm4(uint32_t* r, uint32_t addr) {
    asm volatile("ldmatrix.sync.aligned.m8n8.x4.shared.b16 {%0,%1,%2,%3}, [%4];"
        : "=r"(r[0]), "=r"(r[1]), "=r"(r[2]), "=r"(r[3]) : "r"(addr));
}
__device__ __forceinline__ void mma16816(float* d, const uint32_t* a, uint32_t b0, uint32_t b1) {
    asm volatile("mma.sync.aligned.m16n8k16.row.col.f32.f16.f16.f32 "
        "{%0,%1,%2,%3}, {%4,%5,%6,%7}, {%8,%9}, {%0,%1,%2,%3};"
        : "+f"(d[0]), "+f"(d[1]), "+f"(d[2]), "+f"(d[3])
        : "r"(a[0]), "r"(a[1]), "r"(a[2]), "r"(a[3]), "r"(b0), "r"(b1));
}

// ---------------------------------------------------------------------------
// Conversions: fp32 -> fp16
// ---------------------------------------------------------------------------
__global__ __launch_bounds__(256)
void convert_x_kernel(const float* __restrict__ x)
{
    size_t i4 = (size_t)blockIdx.x * 256 + threadIdx.x;   // 100352*128 float4s
    float4 v = reinterpret_cast<const float4*>(x)[i4];
    __half2 h0 = __floats2half2_rn(v.x, v.y);
    __half2 h1 = __floats2half2_rn(v.z, v.w);
    uint2 u;
    u.x = *reinterpret_cast<uint32_t*>(&h0);
    u.y = *reinterpret_cast<uint32_t*>(&h1);
    *reinterpret_cast<uint2*>(g_Ah + i4 * 4) = u;
}

// W[k][n] -> g_Wh[n][k]
__global__ __launch_bounds__(256)
void convert_W_kernel(const float* __restrict__ W)
{
    int idx = blockIdx.x * 256 + threadIdx.x;   // 512*1536
    int k = idx / NQKV;
    int n = idx % NQKV;
    g_Wh[(size_t)n * DIMC + k] = __float2half_rn(W[idx]);
}

// ---------------------------------------------------------------------------
// HMMA GEMM: g_qkv[M,1536] = Ah[M,512] x Wh[N,512]^T + bias (q cols scaled)
// CTA tile 128x128, BK=32, 8 warps (warp tile 32x64), 3-stage cp.async
// pipeline with ONE __syncthreads per K-chunk.
// smem rows 80 B pitch: rows 0..7 start at banks {0,20,8,28,16,4,24,12}
// -> ldmatrix / STS conflict-free without swizzle.
// ---------------------------------------------------------------------------
#define ROWB         80
#define TILE_BYTES   (128 * ROWB)            // 10240 per operand
#define STAGE_BYTES  (2 * TILE_BYTES)        // A + B = 20480
#define GEMM_SMEM    (3 * STAGE_BYTES)       // 61440
#define NCHUNK       (DIMC / 32)             // 16

__global__ __launch_bounds__(256, 2)
void qkv_gemm_mma(const float* __restrict__ bias)
{
    extern __shared__ char sbuf[];
    const uint32_t sbase = smem_u32(sbuf);

    const int tid  = threadIdx.x;
    const int wid  = tid >> 5;
    const int lane = tid & 31;
    const int wm   = wid >> 1;               // 0..3 -> M offset wm*32
    const int wn   = wid & 1;                // 0..1 -> N offset wn*64
    const int bn0  = blockIdx.x * 128;
    const int bm0  = blockIdx.y * 128;

    // cp.async geometry
    const int rc = tid >> 2;                 // 0..63
    const int jc = tid & 3;                  // 0..3
    const __half* Ag = g_Ah + (size_t)(bm0 + rc) * DIMC + jc * 8;
    const __half* Bg = g_Wh + (size_t)(bn0 + rc) * DIMC + jc * 8;
    const uint32_t sA_off = (uint32_t)(rc * ROWB + jc * 16);

    float acc[2][8][4];
    #pragma unroll
    for (int mi = 0; mi < 2; mi++)
        #pragma unroll
        for (int ni = 0; ni < 8; ni++)
            #pragma unroll
            for (int t = 0; t < 4; t++) acc[mi][ni][t] = 0.0f;

    const uint32_t lrow = (uint32_t)(lane & 15);
    const uint32_t lcol = (uint32_t)((lane & 16) ? 16 : 0);

    #define ISSUE_STAGE(cc) do {                                             \
        const int _k0 = (cc) * 32;                                           \
        const uint32_t _st = sbase + ((cc) % 3) * STAGE_BYTES;               \
        cp16(_st + sA_off,                          Ag + _k0);               \
        cp16(_st + sA_off + 64 * ROWB,              Ag + (size_t)64 * DIMC + _k0); \
        cp16(_st + TILE_BYTES + sA_off,             Bg + _k0);               \
        cp16(_st + TILE_BYTES + sA_off + 64 * ROWB, Bg + (size_t)64 * DIMC + _k0); \
        asm volatile("cp.async.commit_group;" ::: "memory");                 \
    } while (0)

    ISSUE_STAGE(0);
    ISSUE_STAGE(1);

    for (int c = 0; c < NCHUNK; ++c) {
        if (c + 2 < NCHUNK) {
            asm volatile("cp.async.wait_group 1;" ::: "memory");
        } else {
            asm volatile("cp.async.wait_group 0;" ::: "memory");
        }
        __syncthreads();
        if (c + 2 < NCHUNK) ISSUE_STAGE(c + 2);

        const uint32_t sAu = sbase + (c % 3) * STAGE_BYTES;
        const uint32_t sBu = sAu + TILE_BYTES;
        const uint32_t aBase = sAu + (wm * 32 + lrow) * ROWB + lcol;
        const uint32_t bBase = sBu + (wn * 64 + lrow) * ROWB + lcol;

        #pragma unroll
        for (int ks = 0; ks < 2; ks++) {
            uint32_t afr[2][4];
            ldsm4(afr[0], aBase + ks * 32);
            ldsm4(afr[1], aBase + 16 * ROWB + ks * 32);
            #pragma unroll
            for (int pi = 0; pi < 4; pi++) {
                uint32_t bfr[4];
                ldsm4(bfr, bBase + pi * 16 * ROWB + ks * 32);
                mma16816(acc[0][2 * pi + 0], afr[0], bfr[0], bfr[2]);
                mma16816(acc[0][2 * pi + 1], afr[0], bfr[1], bfr[3]);
                mma16816(acc[1][2 * pi + 0], afr[1], bfr[0], bfr[2]);
                mma16816(acc[1][2 * pi + 1], afr[1], bfr[1], bfr[3]);
            }
        }
    }
    #undef ISSUE_STAGE

    // ---- epilogue: bias + scale, store fp32
    const float scale = (bn0 < DIMC) ? SCALEQ : 1.0f;
    const int r0 = bm0 + wm * 32 + (lane >> 2);
    const int c0 = bn0 + wn * 64 + (lane & 3) * 2;
    #pragma unroll
    for (int ni = 0; ni < 8; ni++) {
        const int col = c0 + ni * 8;
        const float2 bb = *reinterpret_cast<const float2*>(&bias[col]);
        #pragma unroll
        for (int mi = 0; mi < 2; mi++) {
            const int row = r0 + mi * 16;
            float2 v0, v1;
            v0.x = (acc[mi][ni][0] + bb.x) * scale;
            v0.y = (acc[mi][ni][1] + bb.y) * scale;
            v1.x = (acc[mi][ni][2] + bb.x) * scale;
            v1.y = (acc[mi][ni][3] + bb.y) * scale;
            *reinterpret_cast<float2*>(&g_qkv[(size_t)row * NQKV + col])       = v0;
            *reinterpret_cast<float2*>(&g_qkv[(size_t)(row + 8) * NQKV + col]) = v1;
        }
    }
}

// ---------------------------------------------------------------------------
// Kernel 2: per-window attention, C-chunked for occupancy 3. (unchanged)
// ---------------------------------------------------------------------------
#define AST 56    // padded S dim
#define QST 60    // Q/K chunk row stride (floats)
#define VST 132   // V row stride (floats)
#define ATTN_SMEM_BYTES ((2 * 128 * QST + AST * AST) * 4)   // 73984

__global__ __launch_bounds__(256, 3)
void attn_kernel(float* __restrict__ out)
{
    extern __shared__ float sm[];
    float* sQ = sm;                       // 128*60
    float* sK = sm + 128 * QST;           // 128*60
    float* sS = sm + 2 * 128 * QST;       // 56*56
    float* sV = sm;                       // overlay on sQ/sK

    const int w   = blockIdx.x;
    const int tid = threadIdx.x;
    const size_t base = (size_t)w * SEQ;

    const int stx = tid & 15;
    const int sty = tid >> 4;
    const bool sact = (stx < 14) && (sty < 14);

    float accS[4][4];
    #pragma unroll
    for (int i = 0; i < 4; i++)
        #pragma unroll
        for (int j = 0; j < 4; j++) accS[i][j] = 0.0f;

    // ---- Phase S: accumulate over 4 channel chunks
    for (int ch = 0; ch < 4; ch++) {
        __syncthreads();
        for (int idx = tid; idx < SEQ * 128; idx += 256) {
            const int i = idx >> 7;
            const int c = idx & 127;
            const float* row = g_qkv + (base + i) * NQKV + ch * 128 + c;
            sQ[c * QST + i] = row[0];
            sK[c * QST + i] = row[DIMC];
        }
        for (int idx = tid; idx < 7 * 128; idx += 256) {
            const int c = idx & 127;
            const int p = idx >> 7;
            sQ[c * QST + SEQ + p] = 0.0f;
            sK[c * QST + SEQ + p] = 0.0f;
        }
        __syncthreads();

        if (sact) {
            const float* qp = sQ + sty * 4;
            const float* kp = sK + stx * 4;
            for (int c = 0; c < 128; c++) {
                float4 qa = *(const float4*)(qp + c * QST);
                float4 kb = *(const float4*)(kp + c * QST);
                float qv[4] = {qa.x, qa.y, qa.z, qa.w};
                float kv[4] = {kb.x, kb.y, kb.z, kb.w};
                #pragma unroll
                for (int i = 0; i < 4; i++)
                    #pragma unroll
                    for (int j = 0; j < 4; j++)
                        accS[i][j] = fmaf(qv[i], kv[j], accS[i][j]);
            }
        }
    }

    if (sact) {
        #pragma unroll
        for (int i = 0; i < 4; i++) {
            float4 v = make_float4(accS[i][0], accS[i][1], accS[i][2], accS[i][3]);
            *(float4*)&sS[(sty * 4 + i) * AST + stx * 4] = v;
        }
    }
    __syncthreads();

    // ---- Softmax: warp per row
    const int wid  = tid >> 5;
    const int lane = tid & 31;
    for (int r = wid; r < SEQ; r += 8) {
        float* row = sS + r * AST;
        const float v0 = (lane < SEQ)      ? row[lane]      : -1e30f;
        const float v1 = (lane + 32 < SEQ) ? row[lane + 32] : -1e30f;
        float mx = fmaxf(v0, v1);
        #pragma unroll
        for (int o = 16; o > 0; o >>= 1)
            mx = fmaxf(mx, __shfl_xor_sync(0xFFFFFFFFu, mx, o));
        const float e0 = (lane < SEQ)      ? __expf(v0 - mx) : 0.0f;
        const float e1 = (lane + 32 < SEQ) ? __expf(v1 - mx) : 0.0f;
        float s = e0 + e1;
        #pragma unroll
        for (int o = 16; o > 0; o >>= 1)
            s += __shfl_xor_sync(0xFFFFFFFFu, s, o);
        const float inv = 1.0f / s;
        if (lane < SEQ)      row[lane]      = e0 * inv;
        if (lane + 32 < AST) row[lane + 32] = e1 * inv;   // pads 49..55 -> 0
    }

    // ---- Phase PV over 4 channel chunks
    const int cl = tid & 127;
    const int hf = tid >> 7;
    const int rb = hf * 25;
    const int nr = hf ? 24 : 25;

    for (int ch = 0; ch < 4; ch++) {
        __syncthreads();
        for (int idx = tid; idx < SEQ * 128; idx += 256) {
            const int i = idx >> 7;
            const int c = idx & 127;
            sV[i * VST + c] = g_qkv[(base + i) * NQKV + 2 * DIMC + ch * 128 + c];
        }
        for (int idx = tid; idx < 7 * 128; idx += 256) {
            const int c = idx & 127;
            const int p = idx >> 7;
            sV[(SEQ + p) * VST + c] = 0.0f;
        }
        __syncthreads();

        #pragma unroll
        for (int g = 0; g < 5; g++) {
            const int r0 = rb + g * 5;
            float acc[5] = {0.0f, 0.0f, 0.0f, 0.0f, 0.0f};
            for (int j4 = 0; j4 < AST; j4 += 4) {
                const float va = sV[(j4 + 0) * VST + cl];
                const float vb = sV[(j4 + 1) * VST + cl];
                const float vc = sV[(j4 + 2) * VST + cl];
                const float vd = sV[(j4 + 3) * VST + cl];
                #pragma unroll
                for (int rr = 0; rr < 5; rr++) {
                    float4 p = *(const float4*)&sS[(r0 + rr) * AST + j4];
                    acc[rr] += p.x * va + p.y * vb + p.z * vc + p.w * vd;
                }
            }
            const int lim = nr - g * 5;
            #pragma unroll
            for (int rr = 0; rr < 5; rr++) {
                if (rr < lim)
                    out[(base + r0 + rr) * DIMC + ch * 128 + cl] = acc[rr];
            }
        }
    }
}

// ---------------------------------------------------------------------------
extern "C" void kernel_launch(void* const* d_in, const int* in_sizes, int n_in,
                              void* d_out, int out_size)
{
    const float* x    = (const float*)d_in[0];
    // d_in[1] = x_all : unused by the reference
    const float* W    = (const float*)d_in[2];
    const float* bias = (const float*)d_in[3];
    float* out        = (float*)d_out;

    cudaFuncSetAttribute(qkv_gemm_mma,
                         cudaFuncAttributeMaxDynamicSharedMemorySize, GEMM_SMEM);
    cudaFuncSetAttribute(attn_kernel,
                         cudaFuncAttributeMaxDynamicSharedMemorySize, ATTN_SMEM_BYTES);

    convert_x_kernel<<<(M_TOTAL * (DIMC / 4)) / 256, 256>>>(x);   // 50176 blocks
    convert_W_kernel<<<(DIMC * NQKV) / 256, 256>>>(W);            // 3072 blocks

    dim3 gemm_grid(NQKV / 128, M_TOTAL / 128);                    // 12 x 784
    qkv_gemm_mma<<<gemm_grid, 256, GEMM_SMEM>>>(bias);

    attn_kernel<<<NWIN, 256, ATTN_SMEM_BYTES>>>(out);
}

// round 8
// speedup vs baseline: 4.3931x; 1.0530x over previous
#include <cuda_runtime.h>
#include <cuda_fp16.h>
#include <cstdint>
#include <math.h>

// Problem constants
#define DIMC     512
#define ZN       1024        // GEMM output cols: [Y | v]
#define M_TOTAL  100352      // 8*256*49
#define SEQ      49
#define NWIN     2048        // 8*256
#define SCALEQ   0.17677669529663687f   // 32^-0.5

// Scratch (__device__ globals: the sanctioned scratch mechanism)
__device__ float  g_Z  [(size_t)M_TOTAL * ZN];     // 411 MB  [Y | v] fp32
__device__ __half g_Ah [(size_t)M_TOTAL * DIMC];   // 103 MB  fp16 x
__device__ __half g_Bh [(size_t)ZN * DIMC];        // 1 MB    B rows: n<512 -> M'[:,n], n>=512 -> Wv[:,n-512]
__device__ float  g_t2 [M_TOTAL];                  // bias-induced column term
__device__ float  g_w2 [DIMC];                     // SCALE * Wk * bq

// ---------------------------------------------------------------------------
// Helpers
// ---------------------------------------------------------------------------
__device__ __forceinline__ uint32_t smem_u32(const void* p) {
    uint32_t a;
    asm("{ .reg .u64 t; cvta.to.shared.u64 t, %1; cvt.u32.u64 %0, t; }" : "=r"(a) : "l"(p));
    return a;
}
__device__ __forceinline__ void cp16(uint32_t s, const void* g) {
    asm volatile("cp.async.cg.shared.global [%0], [%1], 16;" :: "r"(s), "l"(g));
}
__device__ __forceinline__ void ldsm4(uint32_t* r, uint32_t addr) {
    asm volatile("ldmatrix.sync.aligned.m8n8.x4.shared.b16 {%0,%1,%2,%3}, [%4];"
        : "=r"(r[0]), "=r"(r[1]), "=r"(r[2]), "=r"(r[3]) : "r"(addr));
}
__device__ __forceinline__ void mma16816(float* d, const uint32_t* a, uint32_t b0, uint32_t b1) {
    asm volatile("mma.sync.aligned.m16n8k16.row.col.f32.f16.f16.f32 "
        "{%0,%1,%2,%3}, {%4,%5,%6,%7}, {%8,%9}, {%0,%1,%2,%3};"
        : "+f"(d[0]), "+f"(d[1]), "+f"(d[2]), "+f"(d[3])
        : "r"(a[0]), "r"(a[1]), "r"(a[2]), "r"(a[3]), "r"(b0), "r"(b1));
}

// ---------------------------------------------------------------------------
// prep_w2: g_w2[c] = SCALE * sum_a W[c][512+a] * bias[a]
// ---------------------------------------------------------------------------
__global__ __launch_bounds__(256)
void prep_w2_kernel(const float* __restrict__ W, const float* __restrict__ bias)
{
    int c = blockIdx.x * 256 + threadIdx.x;   // 0..511
    const float* row = W + (size_t)c * 1536 + 512;
    float s = 0.0f;
    for (int a = 0; a < DIMC; a++) s += row[a] * bias[a];
    g_w2[c] = SCALEQ * s;
}

// ---------------------------------------------------------------------------
// convert_x: fp32 x -> fp16 g_Ah; also g_t2[m] = x_m . g_w2
// One block = 2 rows (128 float4-threads per row).
// ---------------------------------------------------------------------------
__global__ __launch_bounds__(256)
void convert_x_kernel(const float* __restrict__ x)
{
    __shared__ float red[2][4];
    const int tid = threadIdx.x;
    size_t i4 = (size_t)blockIdx.x * 256 + tid;       // global float4 index
    float4 v = reinterpret_cast<const float4*>(x)[i4];
    const int kq = (int)(i4 & 127);

    __half2 h0 = __floats2half2_rn(v.x, v.y);
    __half2 h1 = __floats2half2_rn(v.z, v.w);
    uint2 u;
    u.x = *reinterpret_cast<uint32_t*>(&h0);
    u.y = *reinterpret_cast<uint32_t*>(&h1);
    *reinterpret_cast<uint2*>(g_Ah + i4 * 4) = u;

    // t2 partial: dot with w2
    float4 wv = *reinterpret_cast<const float4*>(&g_w2[kq * 4]);
    float p = v.x * wv.x + v.y * wv.y + v.z * wv.z + v.w * wv.w;
    #pragma unroll
    for (int o = 16; o > 0; o >>= 1) p += __shfl_down_sync(0xFFFFFFFFu, p, o);
    const int w = tid >> 5;                            // warp 0..7
    if ((tid & 31) == 0) red[w >> 2][w & 3] = p;
    __syncthreads();
    if ((tid & 127) == 0) {
        const int r = tid >> 7;                        // 0 or 1
        g_t2[blockIdx.x * 2 + r] = red[r][0] + red[r][1] + red[r][2] + red[r][3];
    }
}

// ---------------------------------------------------------------------------
// prep_M: M'[c1][c2] = SCALE * sum_a W[c1][a] * W[c2][512+a]
// stored as B rows: g_Bh[c2*512 + c1].  64x64 tile per CTA, 256 threads.
// ---------------------------------------------------------------------------
__global__ __launch_bounds__(256)
void prep_M_kernel(const float* __restrict__ W)
{
    __shared__ float sQ[16][68];   // [a][c1]
    __shared__ float sK[16][68];   // [a][c2]
    const int tid = threadIdx.x;
    const int tx = tid & 15, ty = tid >> 4;
    const int c1b = blockIdx.y * 64;
    const int c2b = blockIdx.x * 64;

    const int r  = tid >> 2;          // 0..63
    const int aq = (tid & 3) * 4;     // 0,4,8,12

    float acc[4][4];
    #pragma unroll
    for (int i = 0; i < 4; i++)
        #pragma unroll
        for (int j = 0; j < 4; j++) acc[i][j] = 0.0f;

    for (int a0 = 0; a0 < DIMC; a0 += 16) {
        __syncthreads();
        float4 wq = *reinterpret_cast<const float4*>(&W[(size_t)(c1b + r) * 1536 + a0 + aq]);
        float4 wk = *reinterpret_cast<const float4*>(&W[(size_t)(c2b + r) * 1536 + 512 + a0 + aq]);
        sQ[aq + 0][r] = wq.x; sQ[aq + 1][r] = wq.y; sQ[aq + 2][r] = wq.z; sQ[aq + 3][r] = wq.w;
        sK[aq + 0][r] = wk.x; sK[aq + 1][r] = wk.y; sK[aq + 2][r] = wk.z; sK[aq + 3][r] = wk.w;
        __syncthreads();

        #pragma unroll
        for (int a = 0; a < 16; a++) {
            float4 q = *reinterpret_cast<const float4*>(&sQ[a][ty * 4]);
            float4 k = *reinterpret_cast<const float4*>(&sK[a][tx * 4]);
            float qa[4] = {q.x, q.y, q.z, q.w};
            float ka[4] = {k.x, k.y, k.z, k.w};
            #pragma unroll
            for (int i = 0; i < 4; i++)
                #pragma unroll
                for (int j = 0; j < 4; j++)
                    acc[i][j] = fmaf(qa[i], ka[j], acc[i][j]);
        }
    }

    #pragma unroll
    for (int j = 0; j < 4; j++) {
        const int c2 = c2b + tx * 4 + j;
        #pragma unroll
        for (int i = 0; i < 4; i++) {
            const int c1 = c1b + ty * 4 + i;
            g_Bh[(size_t)c2 * DIMC + c1] = __float2half_rn(SCALEQ * acc[i][j]);
        }
    }
}

// prep_v: g_Bh[(512+nv)*512 + c] = fp16(W[c][1024+nv])
__global__ __launch_bounds__(256)
void prep_v_kernel(const float* __restrict__ W)
{
    int idx = blockIdx.x * 256 + threadIdx.x;   // 512*512
    int c  = idx >> 9;
    int nv = idx & 511;
    g_Bh[(size_t)(512 + nv) * DIMC + c] = __float2half_rn(W[(size_t)c * 1536 + 1024 + nv]);
}

// ---------------------------------------------------------------------------
// HMMA GEMM: g_Z[M,1024] = Ah[M,512] x Bh[N,512]^T  (+ bv on v half)
// CTA tile 128x128, BK=32, 8 warps, 3-stage cp.async pipeline.
// ---------------------------------------------------------------------------
#define ROWB         80
#define TILE_BYTES   (128 * ROWB)
#define STAGE_BYTES  (2 * TILE_BYTES)
#define GEMM_SMEM    (3 * STAGE_BYTES)       // 61440
#define NCHUNK       (DIMC / 32)             // 16

__global__ __launch_bounds__(256, 2)
void z_gemm_mma(const float* __restrict__ bias)
{
    extern __shared__ char sbuf[];
    const uint32_t sbase = smem_u32(sbuf);

    const int tid  = threadIdx.x;
    const int wid  = tid >> 5;
    const int lane = tid & 31;
    const int wm   = wid >> 1;
    const int wn   = wid & 1;
    const int bn0  = blockIdx.x * 128;
    const int bm0  = blockIdx.y * 128;

    const int rc = tid >> 2;
    const int jc = tid & 3;
    const __half* Ag = g_Ah + (size_t)(bm0 + rc) * DIMC + jc * 8;
    const __half* Bg = g_Bh + (size_t)(bn0 + rc) * DIMC + jc * 8;
    const uint32_t sA_off = (uint32_t)(rc * ROWB + jc * 16);

    float acc[2][8][4];
    #pragma unroll
    for (int mi = 0; mi < 2; mi++)
        #pragma unroll
        for (int ni = 0; ni < 8; ni++)
            #pragma unroll
            for (int t = 0; t < 4; t++) acc[mi][ni][t] = 0.0f;

    const uint32_t lrow = (uint32_t)(lane & 15);
    const uint32_t lcol = (uint32_t)((lane & 16) ? 16 : 0);

    #define ISSUE_STAGE(cc) do {                                             \
        const int _k0 = (cc) * 32;                                           \
        const uint32_t _st = sbase + ((cc) % 3) * STAGE_BYTES;               \
        cp16(_st + sA_off,                          Ag + _k0);               \
        cp16(_st + sA_off + 64 * ROWB,              Ag + (size_t)64 * DIMC + _k0); \
        cp16(_st + TILE_BYTES + sA_off,             Bg + _k0);               \
        cp16(_st + TILE_BYTES + sA_off + 64 * ROWB, Bg + (size_t)64 * DIMC + _k0); \
        asm volatile("cp.async.commit_group;" ::: "memory");                 \
    } while (0)

    ISSUE_STAGE(0);
    ISSUE_STAGE(1);

    for (int c = 0; c < NCHUNK; ++c) {
        if (c + 2 < NCHUNK) {
            asm volatile("cp.async.wait_group 1;" ::: "memory");
        } else {
            asm volatile("cp.async.wait_group 0;" ::: "memory");
        }
        __syncthreads();
        if (c + 2 < NCHUNK) ISSUE_STAGE(c + 2);

        const uint32_t sAu = sbase + (c % 3) * STAGE_BYTES;
        const uint32_t sBu = sAu + TILE_BYTES;
        const uint32_t aBase = sAu + (wm * 32 + lrow) * ROWB + lcol;
        const uint32_t bBase = sBu + (wn * 64 + lrow) * ROWB + lcol;

        #pragma unroll
        for (int ks = 0; ks < 2; ks++) {
            uint32_t afr[2][4];
            ldsm4(afr[0], aBase + ks * 32);
            ldsm4(afr[1], aBase + 16 * ROWB + ks * 32);
            #pragma unroll
            for (int pi = 0; pi < 4; pi++) {
                uint32_t bfr[4];
                ldsm4(bfr, bBase + pi * 16 * ROWB + ks * 32);
                mma16816(acc[0][2 * pi + 0], afr[0], bfr[0], bfr[2]);
                mma16816(acc[0][2 * pi + 1], afr[0], bfr[1], bfr[3]);
                mma16816(acc[1][2 * pi + 0], afr[1], bfr[0], bfr[2]);
                mma16816(acc[1][2 * pi + 1], afr[1], bfr[1], bfr[3]);
            }
        }
    }
    #undef ISSUE_STAGE

    // epilogue: v half gets bias[1024 + (n-512)] = bias[512 + n]; Y half none
    const bool isv = (bn0 >= DIMC);
    const int r0 = bm0 + wm * 32 + (lane >> 2);
    const int c0 = bn0 + wn * 64 + (lane & 3) * 2;
    #pragma unroll
    for (int ni = 0; ni < 8; ni++) {
        const int col = c0 + ni * 8;
        float2 bb = make_float2(0.0f, 0.0f);
        if (isv) bb = *reinterpret_cast<const float2*>(&bias[512 + col]);
        #pragma unroll
        for (int mi = 0; mi < 2; mi++) {
            const int row = r0 + mi * 16;
            float2 v0, v1;
            v0.x = acc[mi][ni][0] + bb.x;
            v0.y = acc[mi][ni][1] + bb.y;
            v1.x = acc[mi][ni][2] + bb.x;
            v1.y = acc[mi][ni][3] + bb.y;
            *reinterpret_cast<float2*>(&g_Z[(size_t)row * ZN + col])       = v0;
            *reinterpret_cast<float2*>(&g_Z[(size_t)(row + 8) * ZN + col]) = v1;
        }
    }
}

// ---------------------------------------------------------------------------
// Attention: Q = Y (Z left half), K = original x (fp32, exact), V = Z right.
// S_ij += t2_j before softmax (row-constant bias terms cancel in softmax).
// ---------------------------------------------------------------------------
#define AST 56
#define QST 60
#define VST 132
#define ATTN_SMEM_BYTES ((2 * 128 * QST + AST * AST + 64) * 4)   // 74240

__global__ __launch_bounds__(256, 3)
void attn_kernel(float* __restrict__ out, const float* __restrict__ x)
{
    extern __shared__ float sm[];
    float* sQ  = sm;                          // 128*60
    float* sK  = sm + 128 * QST;              // 128*60
    float* sS  = sm + 2 * 128 * QST;          // 56*56
    float* sT2 = sm + 2 * 128 * QST + AST * AST;   // 64
    float* sV  = sm;                          // overlay on sQ/sK

    const int w   = blockIdx.x;
    const int tid = threadIdx.x;
    const size_t base = (size_t)w * SEQ;

    if (tid < SEQ) sT2[tid] = g_t2[base + tid];

    const int stx = tid & 15;
    const int sty = tid >> 4;
    const bool sact = (stx < 14) && (sty < 14);

    float accS[4][4];
    #pragma unroll
    for (int i = 0; i < 4; i++)
        #pragma unroll
        for (int j = 0; j < 4; j++) accS[i][j] = 0.0f;

    // ---- Phase S over 4 channel chunks
    for (int ch = 0; ch < 4; ch++) {
        __syncthreads();
        for (int idx = tid; idx < SEQ * 128; idx += 256) {
            const int i = idx >> 7;
            const int c = idx & 127;
            sQ[c * QST + i] = g_Z[(base + i) * ZN + ch * 128 + c];
            sK[c * QST + i] = x[(base + i) * DIMC + ch * 128 + c];
        }
        for (int idx = tid; idx < 7 * 128; idx += 256) {
            const int c = idx & 127;
            const int p = idx >> 7;
            sQ[c * QST + SEQ + p] = 0.0f;
            sK[c * QST + SEQ + p] = 0.0f;
        }
        __syncthreads();

        if (sact) {
            const float* qp = sQ + sty * 4;
            const float* kp = sK + stx * 4;
            for (int c = 0; c < 128; c++) {
                float4 qa = *(const float4*)(qp + c * QST);
                float4 kb = *(const float4*)(kp + c * QST);
                float qv[4] = {qa.x, qa.y, qa.z, qa.w};
                float kv[4] = {kb.x, kb.y, kb.z, kb.w};
                #pragma unroll
                for (int i = 0; i < 4; i++)
                    #pragma unroll
                    for (int j = 0; j < 4; j++)
                        accS[i][j] = fmaf(qv[i], kv[j], accS[i][j]);
            }
        }
    }

    if (sact) {
        #pragma unroll
        for (int i = 0; i < 4; i++) {
            float4 v = make_float4(accS[i][0], accS[i][1], accS[i][2], accS[i][3]);
            *(float4*)&sS[(sty * 4 + i) * AST + stx * 4] = v;
        }
    }
    __syncthreads();

    // ---- Softmax (adds t2_j)
    const int wid  = tid >> 5;
    const int lane = tid & 31;
    for (int r = wid; r < SEQ; r += 8) {
        float* row = sS + r * AST;
        const float v0 = (lane < SEQ)      ? row[lane]      + sT2[lane]      : -1e30f;
        const float v1 = (lane + 32 < SEQ) ? row[lane + 32] + sT2[lane + 32] : -1e30f;
        float mx = fmaxf(v0, v1);
        #pragma unroll
        for (int o = 16; o > 0; o >>= 1)
            mx = fmaxf(mx, __shfl_xor_sync(0xFFFFFFFFu, mx, o));
        const float e0 = (lane < SEQ)      ? __expf(v0 - mx) : 0.0f;
        const float e1 = (lane + 32 < SEQ) ? __expf(v1 - mx) : 0.0f;
        float s = e0 + e1;
        #pragma unroll
        for (int o = 16; o > 0; o >>= 1)
            s += __shfl_xor_sync(0xFFFFFFFFu, s, o);
        const float inv = 1.0f / s;
        if (lane < SEQ)      row[lane]      = e0 * inv;
        if (lane + 32 < AST) row[lane + 32] = e1 * inv;
    }

    // ---- Phase PV over 4 channel chunks (V = Z right half, biased)
    const int cl = tid & 127;
    const int hf = tid >> 7;
    const int rb = hf * 25;
    const int nr = hf ? 24 : 25;

    for (int ch = 0; ch < 4; ch++) {
        __syncthreads();
        for (int idx = tid; idx < SEQ * 128; idx += 256) {
            const int i = idx >> 7;
            const int c = idx & 127;
            sV[i * VST + c] = g_Z[(base + i) * ZN + 512 + ch * 128 + c];
        }
        for (int idx = tid; idx < 7 * 128; idx += 256) {
            const int c = idx & 127;
            const int p = idx >> 7;
            sV[(SEQ + p) * VST + c] = 0.0f;
        }
        __syncthreads();

        #pragma unroll
        for (int g = 0; g < 5; g++) {
            const int r0 = rb + g * 5;
            float acc[5] = {0.0f, 0.0f, 0.0f, 0.0f, 0.0f};
            for (int j4 = 0; j4 < AST; j4 += 4) {
                const float va = sV[(j4 + 0) * VST + cl];
                const float vb = sV[(j4 + 1) * VST + cl];
                const float vc = sV[(j4 + 2) * VST + cl];
                const float vd = sV[(j4 + 3) * VST + cl];
                #pragma unroll
                for (int rr = 0; rr < 5; rr++) {
                    float4 p = *(const float4*)&sS[(r0 + rr) * AST + j4];
                    acc[rr] += p.x * va + p.y * vb + p.z * vc + p.w * vd;
                }
            }
            const int lim = nr - g * 5;
            #pragma unroll
            for (int rr = 0; rr < 5; rr++) {
                if (rr < lim)
                    out[(base + r0 + rr) * DIMC + ch * 128 + cl] = acc[rr];
            }
        }
    }
}

// ---------------------------------------------------------------------------
extern "C" void kernel_launch(void* const* d_in, const int* in_sizes, int n_in,
                              void* d_out, int out_size)
{
    const float* x    = (const float*)d_in[0];
    // d_in[1] = x_all : unused by the reference
    const float* W    = (const float*)d_in[2];
    const float* bias = (const float*)d_in[3];
    float* out        = (float*)d_out;

    cudaFuncSetAttribute(z_gemm_mma,
                         cudaFuncAttributeMaxDynamicSharedMemorySize, GEMM_SMEM);
    cudaFuncSetAttribute(attn_kernel,
                         cudaFuncAttributeMaxDynamicSharedMemorySize, ATTN_SMEM_BYTES);

    prep_w2_kernel<<<2, 256>>>(W, bias);
    convert_x_kernel<<<(M_TOTAL * (DIMC / 4)) / 256, 256>>>(x);   // 50176 blocks
    prep_M_kernel<<<dim3(8, 8), 256>>>(W);
    prep_v_kernel<<<(DIMC * DIMC) / 256, 256>>>(W);               // 1024 blocks

    dim3 gemm_grid(ZN / 128, M_TOTAL / 128);                      // 8 x 784
    z_gemm_mma<<<gemm_grid, 256, GEMM_SMEM>>>(bias);

    attn_kernel<<<NWIN, 256, ATTN_SMEM_BYTES>>>(out, x);
}

// round 10
// speedup vs baseline: 5.8697x; 1.3361x over previous
#include <cuda_runtime.h>
#include <cuda_fp16.h>
#include <cstdint>
#include <math.h>

// Problem constants
#define DIMC     512
#define ZN       1024        // GEMM output cols: [Y | v]
#define M_TOTAL  100352      // 8*256*49
#define SEQ      49
#define NWIN     2048        // 8*256
#define SCALEQ   0.17677669529663687f   // 32^-0.5

// Scratch (__device__ globals: the sanctioned scratch mechanism)
__device__ float  g_Z  [(size_t)M_TOTAL * ZN];     // 411 MB  [Y | v] fp32
__device__ __half g_Ah [(size_t)M_TOTAL * DIMC];   // 103 MB  fp16 x
__device__ __half g_Bh [(size_t)ZN * DIMC];        // 1 MB
__device__ float  g_t2 [M_TOTAL];                  // bias-induced column term
__device__ float  g_w2 [DIMC];                     // SCALE * Wk * bq

// ---------------------------------------------------------------------------
// Helpers
// ---------------------------------------------------------------------------
__device__ __forceinline__ uint32_t smem_u32(const void* p) {
    uint32_t a;
    asm("{ .reg .u64 t; cvta.to.shared.u64 t, %1; cvt.u32.u64 %0, t; }" : "=r"(a) : "l"(p));
    return a;
}
__device__ __forceinline__ void cp16(uint32_t s, const void* g) {
    asm volatile("cp.async.cg.shared.global [%0], [%1], 16;" :: "r"(s), "l"(g));
}
__device__ __forceinline__ void ldsm4(uint32_t* r, uint32_t addr) {
    asm volatile("ldmatrix.sync.aligned.m8n8.x4.shared.b16 {%0,%1,%2,%3}, [%4];"
        : "=r"(r[0]), "=r"(r[1]), "=r"(r[2]), "=r"(r[3]) : "r"(addr));
}
__device__ __forceinline__ void ldsm4t(uint32_t* r, uint32_t addr) {
    asm volatile("ldmatrix.sync.aligned.m8n8.x4.trans.shared.b16 {%0,%1,%2,%3}, [%4];"
        : "=r"(r[0]), "=r"(r[1]), "=r"(r[2]), "=r"(r[3]) : "r"(addr));
}
__device__ __forceinline__ void mma16816(float* d, const uint32_t* a, uint32_t b0, uint32_t b1) {
    asm volatile("mma.sync.aligned.m16n8k16.row.col.f32.f16.f16.f32 "
        "{%0,%1,%2,%3}, {%4,%5,%6,%7}, {%8,%9}, {%0,%1,%2,%3};"
        : "+f"(d[0]), "+f"(d[1]), "+f"(d[2]), "+f"(d[3])
        : "r"(a[0]), "r"(a[1]), "r"(a[2]), "r"(a[3]), "r"(b0), "r"(b1));
}

// ---------------------------------------------------------------------------
// prep_w2: g_w2[c] = SCALE * sum_a W[c][512+a] * bias[a]
// ---------------------------------------------------------------------------
__global__ __launch_bounds__(256)
void prep_w2_kernel(const float* __restrict__ W, const float* __restrict__ bias)
{
    int c = blockIdx.x * 256 + threadIdx.x;   // 0..511
    const float* row = W + (size_t)c * 1536 + 512;
    float s = 0.0f;
    for (int a = 0; a < DIMC; a++) s += row[a] * bias[a];
    g_w2[c] = SCALEQ * s;
}

// ---------------------------------------------------------------------------
// convert_x: fp32 x -> fp16 g_Ah; also g_t2[m] = x_m . g_w2
// ---------------------------------------------------------------------------
__global__ __launch_bounds__(256)
void convert_x_kernel(const float* __restrict__ x)
{
    __shared__ float red[2][4];
    const int tid = threadIdx.x;
    size_t i4 = (size_t)blockIdx.x * 256 + tid;
    float4 v = reinterpret_cast<const float4*>(x)[i4];
    const int kq = (int)(i4 & 127);

    __half2 h0 = __floats2half2_rn(v.x, v.y);
    __half2 h1 = __floats2half2_rn(v.z, v.w);
    uint2 u;
    u.x = *reinterpret_cast<uint32_t*>(&h0);
    u.y = *reinterpret_cast<uint32_t*>(&h1);
    *reinterpret_cast<uint2*>(g_Ah + i4 * 4) = u;

    float4 wv = *reinterpret_cast<const float4*>(&g_w2[kq * 4]);
    float p = v.x * wv.x + v.y * wv.y + v.z * wv.z + v.w * wv.w;
    #pragma unroll
    for (int o = 16; o > 0; o >>= 1) p += __shfl_down_sync(0xFFFFFFFFu, p, o);
    const int w = tid >> 5;
    if ((tid & 31) == 0) red[w >> 2][w & 3] = p;
    __syncthreads();
    if ((tid & 127) == 0) {
        const int r = tid >> 7;
        g_t2[blockIdx.x * 2 + r] = red[r][0] + red[r][1] + red[r][2] + red[r][3];
    }
}

// ---------------------------------------------------------------------------
// prep_M: M'[c1][c2] = SCALE * sum_a W[c1][a] * W[c2][512+a]
// ---------------------------------------------------------------------------
__global__ __launch_bounds__(256)
void prep_M_kernel(const float* __restrict__ W)
{
    __shared__ float sQ[16][68];
    __shared__ float sK[16][68];
    const int tid = threadIdx.x;
    const int tx = tid & 15, ty = tid >> 4;
    const int c1b = blockIdx.y * 64;
    const int c2b = blockIdx.x * 64;

    const int r  = tid >> 2;
    const int aq = (tid & 3) * 4;

    float acc[4][4];
    #pragma unroll
    for (int i = 0; i < 4; i++)
        #pragma unroll
        for (int j = 0; j < 4; j++) acc[i][j] = 0.0f;

    for (int a0 = 0; a0 < DIMC; a0 += 16) {
        __syncthreads();
        float4 wq = *reinterpret_cast<const float4*>(&W[(size_t)(c1b + r) * 1536 + a0 + aq]);
        float4 wk = *reinterpret_cast<const float4*>(&W[(size_t)(c2b + r) * 1536 + 512 + a0 + aq]);
        sQ[aq + 0][r] = wq.x; sQ[aq + 1][r] = wq.y; sQ[aq + 2][r] = wq.z; sQ[aq + 3][r] = wq.w;
        sK[aq + 0][r] = wk.x; sK[aq + 1][r] = wk.y; sK[aq + 2][r] = wk.z; sK[aq + 3][r] = wk.w;
        __syncthreads();

        #pragma unroll
        for (int a = 0; a < 16; a++) {
            float4 q = *reinterpret_cast<const float4*>(&sQ[a][ty * 4]);
            float4 k = *reinterpret_cast<const float4*>(&sK[a][tx * 4]);
            float qa[4] = {q.x, q.y, q.z, q.w};
            float ka[4] = {k.x, k.y, k.z, k.w};
            #pragma unroll
            for (int i = 0; i < 4; i++)
                #pragma unroll
                for (int j = 0; j < 4; j++)
                    acc[i][j] = fmaf(qa[i], ka[j], acc[i][j]);
        }
    }

    #pragma unroll
    for (int j = 0; j < 4; j++) {
        const int c2 = c2b + tx * 4 + j;
        #pragma unroll
        for (int i = 0; i < 4; i++) {
            const int c1 = c1b + ty * 4 + i;
            g_Bh[(size_t)c2 * DIMC + c1] = __float2half_rn(SCALEQ * acc[i][j]);
        }
    }
}

// prep_v: g_Bh[(512+nv)*512 + c] = fp16(W[c][1024+nv])
__global__ __launch_bounds__(256)
void prep_v_kernel(const float* __restrict__ W)
{
    int idx = blockIdx.x * 256 + threadIdx.x;
    int c  = idx >> 9;
    int nv = idx & 511;
    g_Bh[(size_t)(512 + nv) * DIMC + c] = __float2half_rn(W[(size_t)c * 1536 + 1024 + nv]);
}

// ---------------------------------------------------------------------------
// HMMA GEMM: g_Z[M,1024] = Ah[M,512] x Bh[N,512]^T  (+ bv on v half)
// ---------------------------------------------------------------------------
#define ROWB         80
#define TILE_BYTES_G (128 * ROWB)
#define STAGE_BYTES  (2 * TILE_BYTES_G)
#define GEMM_SMEM    (3 * STAGE_BYTES)
#define NCHUNK       (DIMC / 32)

__global__ __launch_bounds__(256, 2)
void z_gemm_mma(const float* __restrict__ bias)
{
    extern __shared__ char sbuf[];
    const uint32_t sbase = smem_u32(sbuf);

    const int tid  = threadIdx.x;
    const int wid  = tid >> 5;
    const int lane = tid & 31;
    const int wm   = wid >> 1;
    const int wn   = wid & 1;
    const int bn0  = blockIdx.x * 128;
    const int bm0  = blockIdx.y * 128;

    const int rc = tid >> 2;
    const int jc = tid & 3;
    const __half* Ag = g_Ah + (size_t)(bm0 + rc) * DIMC + jc * 8;
    const __half* Bg = g_Bh + (size_t)(bn0 + rc) * DIMC + jc * 8;
    const uint32_t sA_off = (uint32_t)(rc * ROWB + jc * 16);

    float acc[2][8][4];
    #pragma unroll
    for (int mi = 0; mi < 2; mi++)
        #pragma unroll
        for (int ni = 0; ni < 8; ni++)
            #pragma unroll
            for (int t = 0; t < 4; t++) acc[mi][ni][t] = 0.0f;

    const uint32_t lrow = (uint32_t)(lane & 15);
    const uint32_t lcol = (uint32_t)((lane & 16) ? 16 : 0);

    #define ISSUE_STAGE(cc) do {                                             \
        const int _k0 = (cc) * 32;                                           \
        const uint32_t _st = sbase + ((cc) % 3) * STAGE_BYTES;               \
        cp16(_st + sA_off,                            Ag + _k0);             \
        cp16(_st + sA_off + 64 * ROWB,                Ag + (size_t)64 * DIMC + _k0); \
        cp16(_st + TILE_BYTES_G + sA_off,             Bg + _k0);             \
        cp16(_st + TILE_BYTES_G + sA_off + 64 * ROWB, Bg + (size_t)64 * DIMC + _k0); \
        asm volatile("cp.async.commit_group;" ::: "memory");                 \
    } while (0)

    ISSUE_STAGE(0);
    ISSUE_STAGE(1);

    for (int c = 0; c < NCHUNK; ++c) {
        if (c + 2 < NCHUNK) {
            asm volatile("cp.async.wait_group 1;" ::: "memory");
        } else {
            asm volatile("cp.async.wait_group 0;" ::: "memory");
        }
        __syncthreads();
        if (c + 2 < NCHUNK) ISSUE_STAGE(c + 2);

        const uint32_t sAu = sbase + (c % 3) * STAGE_BYTES;
        const uint32_t sBu = sAu + TILE_BYTES_G;
        const uint32_t aBase = sAu + (wm * 32 + lrow) * ROWB + lcol;
        const uint32_t bBase = sBu + (wn * 64 + lrow) * ROWB + lcol;

        #pragma unroll
        for (int ks = 0; ks < 2; ks++) {
            uint32_t afr[2][4];
            ldsm4(afr[0], aBase + ks * 32);
            ldsm4(afr[1], aBase + 16 * ROWB + ks * 32);
            #pragma unroll
            for (int pi = 0; pi < 4; pi++) {
                uint32_t bfr[4];
                ldsm4(bfr, bBase + pi * 16 * ROWB + ks * 32);
                mma16816(acc[0][2 * pi + 0], afr[0], bfr[0], bfr[2]);
                mma16816(acc[0][2 * pi + 1], afr[0], bfr[1], bfr[3]);
                mma16816(acc[1][2 * pi + 0], afr[1], bfr[0], bfr[2]);
                mma16816(acc[1][2 * pi + 1], afr[1], bfr[1], bfr[3]);
            }
        }
    }
    #undef ISSUE_STAGE

    const bool isv = (bn0 >= DIMC);
    const int r0 = bm0 + wm * 32 + (lane >> 2);
    const int c0 = bn0 + wn * 64 + (lane & 3) * 2;
    #pragma unroll
    for (int ni = 0; ni < 8; ni++) {
        const int col = c0 + ni * 8;
        float2 bb = make_float2(0.0f, 0.0f);
        if (isv) bb = *reinterpret_cast<const float2*>(&bias[512 + col]);
        #pragma unroll
        for (int mi = 0; mi < 2; mi++) {
            const int row = r0 + mi * 16;
            float2 v0, v1;
            v0.x = acc[mi][ni][0] + bb.x;
            v0.y = acc[mi][ni][1] + bb.y;
            v1.x = acc[mi][ni][2] + bb.x;
            v1.y = acc[mi][ni][3] + bb.y;
            *reinterpret_cast<float2*>(&g_Z[(size_t)row * ZN + col])       = v0;
            *reinterpret_cast<float2*>(&g_Z[(size_t)(row + 8) * ZN + col]) = v1;
        }
    }
}

// ---------------------------------------------------------------------------
// HMMA attention. One CTA per window, 8 warps, seq padded 49->64.
//  S = Qh*Kh + Qh*Kl + Ql*Kh   (Q=Y from Z, K=x; hi/lo fp16 splits)
//  softmax (+t2) -> P fp16 (pitch 72 halves = 144 B, 16-B aligned rows)
//  O = P*Vh + P*Vl             (V from Z right half, hi/lo split)
// smem regions (bytes), TPITCH=272:
//  phase S : Qh@0  Ql@17408  Kh@34816  Kl@52224
//  then    : sS fp32 @0 (64x68f), sP fp16 @17408 (64x72h = 9216 B)
//  phase PV: Vh@34816 Vl@52224
//  sT2 @69632 (64 floats)  -> total 69888
// ---------------------------------------------------------------------------
#define TPITCH   272
#define PPITCH   72          // halves; 144 B rows (ldmatrix needs 16-B aligned)
#define QH_OFF   0
#define QL_OFF   17408
#define KH_OFF   34816
#define KL_OFF   52224
#define SS_OFF   0
#define SP_OFF   17408
#define VH_OFF   34816
#define VL_OFF   52224
#define T2_OFF   69632
#define ATTN_SMEM_BYTES 69888

__global__ __launch_bounds__(256, 2)
void attn_kernel(float* __restrict__ out, const float* __restrict__ x)
{
    extern __shared__ char smb[];
    const uint32_t sbase = smem_u32(smb);

    const int w    = blockIdx.x;
    const int tid  = threadIdx.x;
    const int wid  = tid >> 5;
    const int lane = tid & 31;
    const int wm   = wid >> 1;          // 0..3 : M tile (rows wm*16)
    const int wn   = wid & 1;           // 0..1
    const size_t base = (size_t)w * SEQ;

    float* sT2 = reinterpret_cast<float*>(smb + T2_OFF);
    if (tid < SEQ) sT2[tid] = g_t2[base + tid];

    const uint32_t lrow = (uint32_t)(lane & 15);
    const uint32_t lcol = (uint32_t)((lane & 16) ? 16 : 0);

    float accS[4][4];
    #pragma unroll
    for (int nt = 0; nt < 4; nt++)
        #pragma unroll
        for (int t = 0; t < 4; t++) accS[nt][t] = 0.0f;

    // ================= Phase S: 4 channel chunks of 128 =================
    for (int ch = 0; ch < 4; ch++) {
        __syncthreads();
        for (int idx = tid; idx < 64 * 64; idx += 256) {
            const int i  = idx >> 6;
            const int c2 = (idx & 63) * 2;         // even channel index
            float2 qv = make_float2(0.0f, 0.0f);
            float2 kv = make_float2(0.0f, 0.0f);
            if (i < SEQ) {
                qv = *reinterpret_cast<const float2*>(&g_Z[(base + i) * ZN + ch * 128 + c2]);
                kv = *reinterpret_cast<const float2*>(&x[(base + i) * DIMC + ch * 128 + c2]);
            }
            __half2 qh = __floats2half2_rn(qv.x, qv.y);
            __half2 ql = __floats2half2_rn(qv.x - __low2float(qh), qv.y - __high2float(qh));
            __half2 kh = __floats2half2_rn(kv.x, kv.y);
            __half2 kl = __floats2half2_rn(kv.x - __low2float(kh), kv.y - __high2float(kh));
            const uint32_t o = (uint32_t)(i * TPITCH + c2 * 2);
            *reinterpret_cast<__half2*>(smb + QH_OFF + o) = qh;
            *reinterpret_cast<__half2*>(smb + QL_OFF + o) = ql;
            *reinterpret_cast<__half2*>(smb + KH_OFF + o) = kh;
            *reinterpret_cast<__half2*>(smb + KL_OFF + o) = kl;
        }
        __syncthreads();

        const uint32_t aQh = sbase + QH_OFF + (wm * 16 + lrow) * TPITCH + lcol;
        const uint32_t aQl = aQh + (QL_OFF - QH_OFF);
        const uint32_t bKh = sbase + KH_OFF + (wn * 32 + lrow) * TPITCH + lcol;
        const uint32_t bKl = bKh + (KL_OFF - KH_OFF);

        #pragma unroll
        for (int ks = 0; ks < 8; ks++) {
            const uint32_t off = ks * 32;
            uint32_t qh[4], ql[4];
            ldsm4(qh, aQh + off);
            ldsm4(ql, aQl + off);
            #pragma unroll
            for (int g = 0; g < 2; g++) {
                uint32_t kh[4], kl[4];
                ldsm4(kh, bKh + g * 16 * TPITCH + off);
                ldsm4(kl, bKl + g * 16 * TPITCH + off);
                mma16816(accS[g * 2 + 0], qh, kh[0], kh[2]);
                mma16816(accS[g * 2 + 1], qh, kh[1], kh[3]);
                mma16816(accS[g * 2 + 0], qh, kl[0], kl[2]);
                mma16816(accS[g * 2 + 1], qh, kl[1], kl[3]);
                mma16816(accS[g * 2 + 0], ql, kh[0], kh[2]);
                mma16816(accS[g * 2 + 1], ql, kh[1], kh[3]);
            }
        }
    }

    // ---- store S to smem (fp32, pitch 68 floats) ----
    __syncthreads();
    float* sS = reinterpret_cast<float*>(smb + SS_OFF);
    {
        const int fr = lane >> 2;
        const int fc = (lane & 3) * 2;
        #pragma unroll
        for (int nt = 0; nt < 4; nt++) {
            const int col = wn * 32 + nt * 8 + fc;
            *reinterpret_cast<float2*>(&sS[(wm * 16 + fr) * 68 + col]) =
                make_float2(accS[nt][0], accS[nt][1]);
            *reinterpret_cast<float2*>(&sS[(wm * 16 + fr + 8) * 68 + col]) =
                make_float2(accS[nt][2], accS[nt][3]);
        }
    }
    __syncthreads();

    // ---- softmax (adds t2), write P fp16 (pitch 72 halves) ----
    __half* sP = reinterpret_cast<__half*>(smb + SP_OFF);
    for (int r = wid; r < 64; r += 8) {
        const float* row = sS + r * 68;
        const float v0 = (lane < SEQ)      ? row[lane]      + sT2[lane]      : -1e30f;
        const float v1 = (lane + 32 < SEQ) ? row[lane + 32] + sT2[lane + 32] : -1e30f;
        float mx = fmaxf(v0, v1);
        #pragma unroll
        for (int o = 16; o > 0; o >>= 1)
            mx = fmaxf(mx, __shfl_xor_sync(0xFFFFFFFFu, mx, o));
        const float e0 = (lane < SEQ)      ? __expf(v0 - mx) : 0.0f;
        const float e1 = (lane + 32 < SEQ) ? __expf(v1 - mx) : 0.0f;
        float s = e0 + e1;
        #pragma unroll
        for (int o = 16; o > 0; o >>= 1)
            s += __shfl_xor_sync(0xFFFFFFFFu, s, o);
        const float inv = 1.0f / s;
        sP[r * PPITCH + lane]      = __float2half_rn(e0 * inv);
        sP[r * PPITCH + lane + 32] = __float2half_rn(e1 * inv);
    }

    // ================= Phase PV: 4 channel chunks of 128 =================
    for (int ch = 0; ch < 4; ch++) {
        __syncthreads();
        for (int idx = tid; idx < 64 * 64; idx += 256) {
            const int j  = idx >> 6;
            const int c2 = (idx & 63) * 2;
            float2 vv = make_float2(0.0f, 0.0f);
            if (j < SEQ)
                vv = *reinterpret_cast<const float2*>(&g_Z[(base + j) * ZN + 512 + ch * 128 + c2]);
            __half2 vh = __floats2half2_rn(vv.x, vv.y);
            __half2 vl = __floats2half2_rn(vv.x - __low2float(vh), vv.y - __high2float(vh));
            const uint32_t o = (uint32_t)(j * TPITCH + c2 * 2);
            *reinterpret_cast<__half2*>(smb + VH_OFF + o) = vh;
            *reinterpret_cast<__half2*>(smb + VL_OFF + o) = vl;
        }
        __syncthreads();

        float accv[8][4];
        #pragma unroll
        for (int nt = 0; nt < 8; nt++)
            #pragma unroll
            for (int t = 0; t < 4; t++) accv[nt][t] = 0.0f;

        const uint32_t aP0 = sbase + SP_OFF + (wm * 16 + lrow) * (PPITCH * 2) + lcol;
        #pragma unroll
        for (int ks = 0; ks < 4; ks++) {
            uint32_t pf[4];
            ldsm4(pf, aP0 + ks * 32);
            #pragma unroll
            for (int g = 0; g < 4; g++) {
                const uint32_t vaddr = sbase + VH_OFF + (ks * 16 + lrow) * TPITCH
                                     + (uint32_t)((wn * 64 + g * 16 + 8 * (lane >> 4)) * 2);
                uint32_t vh[4], vl[4];
                ldsm4t(vh, vaddr);
                ldsm4t(vl, vaddr + (VL_OFF - VH_OFF));
                mma16816(accv[g * 2 + 0], pf, vh[0], vh[1]);
                mma16816(accv[g * 2 + 1], pf, vh[2], vh[3]);
                mma16816(accv[g * 2 + 0], pf, vl[0], vl[1]);
                mma16816(accv[g * 2 + 1], pf, vl[2], vl[3]);
            }
        }

        // epilogue
        const int fr = lane >> 2;
        const int fc = (lane & 3) * 2;
        const int r0 = wm * 16 + fr;
        #pragma unroll
        for (int nt = 0; nt < 8; nt++) {
            const int col = ch * 128 + wn * 64 + (nt >> 1) * 16 + (nt & 1) * 8 + fc;
            if (r0 < SEQ)
                *reinterpret_cast<float2*>(&out[(base + r0) * DIMC + col]) =
                    make_float2(accv[nt][0], accv[nt][1]);
            if (r0 + 8 < SEQ)
                *reinterpret_cast<float2*>(&out[(base + r0 + 8) * DIMC + col]) =
                    make_float2(accv[nt][2], accv[nt][3]);
        }
    }
}

// ---------------------------------------------------------------------------
extern "C" void kernel_launch(void* const* d_in, const int* in_sizes, int n_in,
                              void* d_out, int out_size)
{
    const float* x    = (const float*)d_in[0];
    // d_in[1] = x_all : unused by the reference
    const float* W    = (const float*)d_in[2];
    const float* bias = (const float*)d_in[3];
    float* out        = (float*)d_out;

    cudaFuncSetAttribute(z_gemm_mma,
                         cudaFuncAttributeMaxDynamicSharedMemorySize, GEMM_SMEM);
    cudaFuncSetAttribute(attn_kernel,
                         cudaFuncAttributeMaxDynamicSharedMemorySize, ATTN_SMEM_BYTES);

    prep_w2_kernel<<<2, 256>>>(W, bias);
    convert_x_kernel<<<(M_TOTAL * (DIMC / 4)) / 256, 256>>>(x);   // 50176 blocks
    prep_M_kernel<<<dim3(8, 8), 256>>>(W);
    prep_v_kernel<<<(DIMC * DIMC) / 256, 256>>>(W);               // 1024 blocks

    dim3 gemm_grid(ZN / 128, M_TOTAL / 128);                      // 8 x 784
    z_gemm_mma<<<gemm_grid, 256, GEMM_SMEM>>>(bias);

    attn_kernel<<<NWIN, 256, ATTN_SMEM_BYTES>>>(out, x);
}

// round 11
// speedup vs baseline: 6.7605x; 1.1518x over previous
#include <cuda_runtime.h>
#include <cuda_fp16.h>
#include <cstdint>
#include <math.h>

// Problem constants
#define DIMC     512
#define M_TOTAL  100352      // 8*256*49
#define SEQ      49
#define NWIN     2048        // 8*256
#define SCALEQ   0.17677669529663687f   // 32^-0.5

// Scratch (__device__ globals)
__device__ __half g_Ah [(size_t)M_TOTAL * DIMC];   // xh : GEMM A operand AND attn K-hi
__device__ __half g_Al [(size_t)M_TOTAL * DIMC];   // xl : attn K-lo
__device__ __half g_Yh [(size_t)M_TOTAL * DIMC];   // Y hi  (Q)
__device__ __half g_Yl [(size_t)M_TOTAL * DIMC];   // Y lo
__device__ __half g_Vh [(size_t)M_TOTAL * DIMC];   // v (+bias) fp16
__device__ __half g_Bh [(size_t)1024 * DIMC];      // GEMM B rows: n<512 -> M'[:,n], else Wv
__device__ float  g_t2 [M_TOTAL];
__device__ float  g_w2 [DIMC];

// ---------------------------------------------------------------------------
// Helpers
// ---------------------------------------------------------------------------
__device__ __forceinline__ uint32_t smem_u32(const void* p) {
    uint32_t a;
    asm("{ .reg .u64 t; cvta.to.shared.u64 t, %1; cvt.u32.u64 %0, t; }" : "=r"(a) : "l"(p));
    return a;
}
__device__ __forceinline__ void cp16(uint32_t s, const void* g) {
    asm volatile("cp.async.cg.shared.global [%0], [%1], 16;" :: "r"(s), "l"(g));
}
__device__ __forceinline__ void ldsm4(uint32_t* r, uint32_t addr) {
    asm volatile("ldmatrix.sync.aligned.m8n8.x4.shared.b16 {%0,%1,%2,%3}, [%4];"
        : "=r"(r[0]), "=r"(r[1]), "=r"(r[2]), "=r"(r[3]) : "r"(addr));
}
__device__ __forceinline__ void ldsm4t(uint32_t* r, uint32_t addr) {
    asm volatile("ldmatrix.sync.aligned.m8n8.x4.trans.shared.b16 {%0,%1,%2,%3}, [%4];"
        : "=r"(r[0]), "=r"(r[1]), "=r"(r[2]), "=r"(r[3]) : "r"(addr));
}
__device__ __forceinline__ void mma16816(float* d, const uint32_t* a, uint32_t b0, uint32_t b1) {
    asm volatile("mma.sync.aligned.m16n8k16.row.col.f32.f16.f16.f32 "
        "{%0,%1,%2,%3}, {%4,%5,%6,%7}, {%8,%9}, {%0,%1,%2,%3};"
        : "+f"(d[0]), "+f"(d[1]), "+f"(d[2]), "+f"(d[3])
        : "r"(a[0]), "r"(a[1]), "r"(a[2]), "r"(a[3]), "r"(b0), "r"(b1));
}

// ---------------------------------------------------------------------------
// prep_w2: g_w2[c] = SCALE * sum_a W[c][512+a] * bias[a]
// ---------------------------------------------------------------------------
__global__ __launch_bounds__(256)
void prep_w2_kernel(const float* __restrict__ W, const float* __restrict__ bias)
{
    int c = blockIdx.x * 256 + threadIdx.x;
    const float* row = W + (size_t)c * 1536 + 512;
    float s = 0.0f;
    for (int a = 0; a < DIMC; a++) s += row[a] * bias[a];
    g_w2[c] = SCALEQ * s;
}

// ---------------------------------------------------------------------------
// convert_x: x -> g_Ah (hi) + g_Al (lo); g_t2[m] = x_m . g_w2
// ---------------------------------------------------------------------------
__global__ __launch_bounds__(256)
void convert_x_kernel(const float* __restrict__ x)
{
    __shared__ float red[2][4];
    const int tid = threadIdx.x;
    size_t i4 = (size_t)blockIdx.x * 256 + tid;
    float4 v = reinterpret_cast<const float4*>(x)[i4];
    const int kq = (int)(i4 & 127);

    __half2 h0 = __floats2half2_rn(v.x, v.y);
    __half2 h1 = __floats2half2_rn(v.z, v.w);
    __half2 l0 = __floats2half2_rn(v.x - __low2float(h0), v.y - __high2float(h0));
    __half2 l1 = __floats2half2_rn(v.z - __low2float(h1), v.w - __high2float(h1));
    uint2 uh, ul;
    uh.x = *reinterpret_cast<uint32_t*>(&h0);
    uh.y = *reinterpret_cast<uint32_t*>(&h1);
    ul.x = *reinterpret_cast<uint32_t*>(&l0);
    ul.y = *reinterpret_cast<uint32_t*>(&l1);
    *reinterpret_cast<uint2*>(g_Ah + i4 * 4) = uh;
    *reinterpret_cast<uint2*>(g_Al + i4 * 4) = ul;

    float4 wv = *reinterpret_cast<const float4*>(&g_w2[kq * 4]);
    float p = v.x * wv.x + v.y * wv.y + v.z * wv.z + v.w * wv.w;
    #pragma unroll
    for (int o = 16; o > 0; o >>= 1) p += __shfl_down_sync(0xFFFFFFFFu, p, o);
    const int w = tid >> 5;
    if ((tid & 31) == 0) red[w >> 2][w & 3] = p;
    __syncthreads();
    if ((tid & 127) == 0) {
        const int r = tid >> 7;
        g_t2[blockIdx.x * 2 + r] = red[r][0] + red[r][1] + red[r][2] + red[r][3];
    }
}

// ---------------------------------------------------------------------------
// prep_M: M'[c1][c2] = SCALE * sum_a W[c1][a] * W[c2][512+a]
// ---------------------------------------------------------------------------
__global__ __launch_bounds__(256)
void prep_M_kernel(const float* __restrict__ W)
{
    __shared__ float sQ[16][68];
    __shared__ float sK[16][68];
    const int tid = threadIdx.x;
    const int tx = tid & 15, ty = tid >> 4;
    const int c1b = blockIdx.y * 64;
    const int c2b = blockIdx.x * 64;

    const int r  = tid >> 2;
    const int aq = (tid & 3) * 4;

    float acc[4][4];
    #pragma unroll
    for (int i = 0; i < 4; i++)
        #pragma unroll
        for (int j = 0; j < 4; j++) acc[i][j] = 0.0f;

    for (int a0 = 0; a0 < DIMC; a0 += 16) {
        __syncthreads();
        float4 wq = *reinterpret_cast<const float4*>(&W[(size_t)(c1b + r) * 1536 + a0 + aq]);
        float4 wk = *reinterpret_cast<const float4*>(&W[(size_t)(c2b + r) * 1536 + 512 + a0 + aq]);
        sQ[aq + 0][r] = wq.x; sQ[aq + 1][r] = wq.y; sQ[aq + 2][r] = wq.z; sQ[aq + 3][r] = wq.w;
        sK[aq + 0][r] = wk.x; sK[aq + 1][r] = wk.y; sK[aq + 2][r] = wk.z; sK[aq + 3][r] = wk.w;
        __syncthreads();

        #pragma unroll
        for (int a = 0; a < 16; a++) {
            float4 q = *reinterpret_cast<const float4*>(&sQ[a][ty * 4]);
            float4 k = *reinterpret_cast<const float4*>(&sK[a][tx * 4]);
            float qa[4] = {q.x, q.y, q.z, q.w};
            float ka[4] = {k.x, k.y, k.z, k.w};
            #pragma unroll
            for (int i = 0; i < 4; i++)
                #pragma unroll
                for (int j = 0; j < 4; j++)
                    acc[i][j] = fmaf(qa[i], ka[j], acc[i][j]);
        }
    }

    #pragma unroll
    for (int j = 0; j < 4; j++) {
        const int c2 = c2b + tx * 4 + j;
        #pragma unroll
        for (int i = 0; i < 4; i++) {
            const int c1 = c1b + ty * 4 + i;
            g_Bh[(size_t)c2 * DIMC + c1] = __float2half_rn(SCALEQ * acc[i][j]);
        }
    }
}

// prep_v: g_Bh[(512+nv)*512 + c] = fp16(W[c][1024+nv])
__global__ __launch_bounds__(256)
void prep_v_kernel(const float* __restrict__ W)
{
    int idx = blockIdx.x * 256 + threadIdx.x;
    int c  = idx >> 9;
    int nv = idx & 511;
    g_Bh[(size_t)(512 + nv) * DIMC + c] = __float2half_rn(W[(size_t)c * 1536 + 1024 + nv]);
}

// ---------------------------------------------------------------------------
// HMMA GEMM: [Y | v] = Ah[M,512] x Bh[N,512]^T; epilogue -> fp16 hi/lo stores
// ---------------------------------------------------------------------------
#define ROWB         80
#define TILE_BYTES_G (128 * ROWB)
#define STAGE_BYTES  (2 * TILE_BYTES_G)
#define GEMM_SMEM    (3 * STAGE_BYTES)
#define NCHUNK       (DIMC / 32)

__global__ __launch_bounds__(256, 2)
void z_gemm_mma(const float* __restrict__ bias)
{
    extern __shared__ char sbuf[];
    const uint32_t sbase = smem_u32(sbuf);

    const int tid  = threadIdx.x;
    const int wid  = tid >> 5;
    const int lane = tid & 31;
    const int wm   = wid >> 1;
    const int wn   = wid & 1;
    const int bn0  = blockIdx.x * 128;
    const int bm0  = blockIdx.y * 128;

    const int rc = tid >> 2;
    const int jc = tid & 3;
    const __half* Ag = g_Ah + (size_t)(bm0 + rc) * DIMC + jc * 8;
    const __half* Bg = g_Bh + (size_t)(bn0 + rc) * DIMC + jc * 8;
    const uint32_t sA_off = (uint32_t)(rc * ROWB + jc * 16);

    float acc[2][8][4];
    #pragma unroll
    for (int mi = 0; mi < 2; mi++)
        #pragma unroll
        for (int ni = 0; ni < 8; ni++)
            #pragma unroll
            for (int t = 0; t < 4; t++) acc[mi][ni][t] = 0.0f;

    const uint32_t lrow = (uint32_t)(lane & 15);
    const uint32_t lcol = (uint32_t)((lane & 16) ? 16 : 0);

    #define ISSUE_STAGE(cc) do {                                             \
        const int _k0 = (cc) * 32;                                           \
        const uint32_t _st = sbase + ((cc) % 3) * STAGE_BYTES;               \
        cp16(_st + sA_off,                            Ag + _k0);             \
        cp16(_st + sA_off + 64 * ROWB,                Ag + (size_t)64 * DIMC + _k0); \
        cp16(_st + TILE_BYTES_G + sA_off,             Bg + _k0);             \
        cp16(_st + TILE_BYTES_G + sA_off + 64 * ROWB, Bg + (size_t)64 * DIMC + _k0); \
        asm volatile("cp.async.commit_group;" ::: "memory");                 \
    } while (0)

    ISSUE_STAGE(0);
    ISSUE_STAGE(1);

    for (int c = 0; c < NCHUNK; ++c) {
        if (c + 2 < NCHUNK) {
            asm volatile("cp.async.wait_group 1;" ::: "memory");
        } else {
            asm volatile("cp.async.wait_group 0;" ::: "memory");
        }
        __syncthreads();
        if (c + 2 < NCHUNK) ISSUE_STAGE(c + 2);

        const uint32_t sAu = sbase + (c % 3) * STAGE_BYTES;
        const uint32_t sBu = sAu + TILE_BYTES_G;
        const uint32_t aBase = sAu + (wm * 32 + lrow) * ROWB + lcol;
        const uint32_t bBase = sBu + (wn * 64 + lrow) * ROWB + lcol;

        #pragma unroll
        for (int ks = 0; ks < 2; ks++) {
            uint32_t afr[2][4];
            ldsm4(afr[0], aBase + ks * 32);
            ldsm4(afr[1], aBase + 16 * ROWB + ks * 32);
            #pragma unroll
            for (int pi = 0; pi < 4; pi++) {
                uint32_t bfr[4];
                ldsm4(bfr, bBase + pi * 16 * ROWB + ks * 32);
                mma16816(acc[0][2 * pi + 0], afr[0], bfr[0], bfr[2]);
                mma16816(acc[0][2 * pi + 1], afr[0], bfr[1], bfr[3]);
                mma16816(acc[1][2 * pi + 0], afr[1], bfr[0], bfr[2]);
                mma16816(acc[1][2 * pi + 1], afr[1], bfr[1], bfr[3]);
            }
        }
    }
    #undef ISSUE_STAGE

    // ---- epilogue: Y half -> hi/lo fp16; v half -> (+bias) fp16
    const bool isv = (bn0 >= DIMC);
    const int r0 = bm0 + wm * 32 + (lane >> 2);
    const int c0 = bn0 + wn * 64 + (lane & 3) * 2;
    #pragma unroll
    for (int ni = 0; ni < 8; ni++) {
        const int col = c0 + ni * 8;
        float2 bb = make_float2(0.0f, 0.0f);
        if (isv) bb = *reinterpret_cast<const float2*>(&bias[512 + col]);
        #pragma unroll
        for (int mi = 0; mi < 2; mi++) {
            const int row = r0 + mi * 16;
            #pragma unroll
            for (int h = 0; h < 2; h++) {
                const float vx = acc[mi][ni][2 * h + 0] + bb.x;
                const float vy = acc[mi][ni][2 * h + 1] + bb.y;
                const size_t o = (size_t)(row + 8 * h) * DIMC + (col - (isv ? DIMC : 0));
                __half2 hh = __floats2half2_rn(vx, vy);
                if (isv) {
                    *reinterpret_cast<__half2*>(&g_Vh[o]) = hh;
                } else {
                    __half2 ll = __floats2half2_rn(vx - __low2float(hh), vy - __high2float(hh));
                    *reinterpret_cast<__half2*>(&g_Yh[o]) = hh;
                    *reinterpret_cast<__half2*>(&g_Yl[o]) = ll;
                }
            }
        }
    }
}

// ---------------------------------------------------------------------------
// HMMA attention. One CTA per window, 8 warps, seq padded 49->64, occ 3.
//  S = Qh*Kh + Qh*Kl + Ql*Kh   (pre-split fp16, cp.async staged)
//  softmax (+t2) -> P fp16 (pitch 72 halves)
//  O = P*Vh                    (single-term PV)
// smem: Qh@0 Ql@17408 Kh@34816 Kl@52224 (TPITCH=272)
//       then sS fp32 @0 (64x68f), sP @17408 (64x72h); Vh reuses KH region
//       sT2 @69632 -> total 69888
// ---------------------------------------------------------------------------
#define TPITCH   272
#define PPITCH   72
#define QH_OFF   0
#define QL_OFF   17408
#define KH_OFF   34816
#define KL_OFF   52224
#define SS_OFF   0
#define SP_OFF   17408
#define VH_OFF   34816
#define T2_OFF   69632
#define ATTN_SMEM_BYTES 69888

__global__ __launch_bounds__(256, 3)
void attn_kernel(float* __restrict__ out)
{
    extern __shared__ char smb[];
    const uint32_t sbase = smem_u32(smb);

    const int w    = blockIdx.x;
    const int tid  = threadIdx.x;
    const int wid  = tid >> 5;
    const int lane = tid & 31;
    const int wm   = wid >> 1;
    const int wn   = wid & 1;
    const size_t base = (size_t)w * SEQ;

    float* sT2 = reinterpret_cast<float*>(smb + T2_OFF);
    if (tid < SEQ) sT2[tid] = g_t2[base + tid];

    // zero pad rows 49..63 of the 4 tile regions (done once; staging never
    // touches them, and Vh reuses the KH region so its pads stay zero too)
    for (int idx = tid; idx < 3840; idx += 256) {
        const int region = idx / 960;            // 0..3
        const int rem    = idx % 960;
        const uint32_t off = (uint32_t)region * 17408u;
        *reinterpret_cast<uint32_t*>(smb + off + (49 + rem / 64) * TPITCH + (rem % 64) * 4) = 0;
    }

    const uint32_t lrow = (uint32_t)(lane & 15);
    const uint32_t lcol = (uint32_t)((lane & 16) ? 16 : 0);

    #define STAGE_TILE(gp, soff) \
        for (int t = tid; t < 784; t += 256) { \
            const int row = t >> 4; const int ck = t & 15; \
            cp16(sbase + (soff) + row * TPITCH + ck * 16, \
                 (gp) + (size_t)(base + row) * DIMC + ch * 128 + ck * 8); \
        }

    float accS[4][4];
    #pragma unroll
    for (int nt = 0; nt < 4; nt++)
        #pragma unroll
        for (int t = 0; t < 4; t++) accS[nt][t] = 0.0f;

    // ================= Phase S: 4 channel chunks of 128 =================
    for (int ch = 0; ch < 4; ch++) {
        __syncthreads();   // prior chunk's ldmatrix reads (and pad zeroing) done
        STAGE_TILE(g_Yh, QH_OFF)
        STAGE_TILE(g_Yl, QL_OFF)
        STAGE_TILE(g_Ah, KH_OFF)
        STAGE_TILE(g_Al, KL_OFF)
        asm volatile("cp.async.commit_group;" ::: "memory");
        asm volatile("cp.async.wait_group 0;" ::: "memory");
        __syncthreads();

        const uint32_t aQh = sbase + QH_OFF + (wm * 16 + lrow) * TPITCH + lcol;
        const uint32_t aQl = aQh + (QL_OFF - QH_OFF);
        const uint32_t bKh = sbase + KH_OFF + (wn * 32 + lrow) * TPITCH + lcol;
        const uint32_t bKl = bKh + (KL_OFF - KH_OFF);

        #pragma unroll
        for (int ks = 0; ks < 8; ks++) {
            const uint32_t off = ks * 32;
            uint32_t qh[4], ql[4];
            ldsm4(qh, aQh + off);
            ldsm4(ql, aQl + off);
            #pragma unroll
            for (int g = 0; g < 2; g++) {
                uint32_t kh[4], kl[4];
                ldsm4(kh, bKh + g * 16 * TPITCH + off);
                ldsm4(kl, bKl + g * 16 * TPITCH + off);
                mma16816(accS[g * 2 + 0], qh, kh[0], kh[2]);
                mma16816(accS[g * 2 + 1], qh, kh[1], kh[3]);
                mma16816(accS[g * 2 + 0], qh, kl[0], kl[2]);
                mma16816(accS[g * 2 + 1], qh, kl[1], kl[3]);
                mma16816(accS[g * 2 + 0], ql, kh[0], kh[2]);
                mma16816(accS[g * 2 + 1], ql, kh[1], kh[3]);
            }
        }
    }

    // ---- store S to smem (fp32, pitch 68 floats) ----
    __syncthreads();
    float* sS = reinterpret_cast<float*>(smb + SS_OFF);
    {
        const int fr = lane >> 2;
        const int fc = (lane & 3) * 2;
        #pragma unroll
        for (int nt = 0; nt < 4; nt++) {
            const int col = wn * 32 + nt * 8 + fc;
            *reinterpret_cast<float2*>(&sS[(wm * 16 + fr) * 68 + col]) =
                make_float2(accS[nt][0], accS[nt][1]);
            *reinterpret_cast<float2*>(&sS[(wm * 16 + fr + 8) * 68 + col]) =
                make_float2(accS[nt][2], accS[nt][3]);
        }
    }
    __syncthreads();

    // ---- softmax (adds t2), write P fp16 ----
    __half* sP = reinterpret_cast<__half*>(smb + SP_OFF);
    for (int r = wid; r < 64; r += 8) {
        const float* row = sS + r * 68;
        const float v0 = (lane < SEQ)      ? row[lane]      + sT2[lane]      : -1e30f;
        const float v1 = (lane + 32 < SEQ) ? row[lane + 32] + sT2[lane + 32] : -1e30f;
        float mx = fmaxf(v0, v1);
        #pragma unroll
        for (int o = 16; o > 0; o >>= 1)
            mx = fmaxf(mx, __shfl_xor_sync(0xFFFFFFFFu, mx, o));
        const float e0 = (lane < SEQ)      ? __expf(v0 - mx) : 0.0f;
        const float e1 = (lane + 32 < SEQ) ? __expf(v1 - mx) : 0.0f;
        float s = e0 + e1;
        #pragma unroll
        for (int o = 16; o > 0; o >>= 1)
            s += __shfl_xor_sync(0xFFFFFFFFu, s, o);
        const float inv = 1.0f / s;
        sP[r * PPITCH + lane]      = __float2half_rn(e0 * inv);
        sP[r * PPITCH + lane + 32] = __float2half_rn(e1 * inv);
    }

    // ================= Phase PV: 4 channel chunks of 128 =================
    for (int ch = 0; ch < 4; ch++) {
        __syncthreads();   // softmax writes / prior chunk reads done
        STAGE_TILE(g_Vh, VH_OFF)
        asm volatile("cp.async.commit_group;" ::: "memory");
        asm volatile("cp.async.wait_group 0;" ::: "memory");
        __syncthreads();

        float accv[8][4];
        #pragma unroll
        for (int nt = 0; nt < 8; nt++)
            #pragma unroll
            for (int t = 0; t < 4; t++) accv[nt][t] = 0.0f;

        const uint32_t aP0 = sbase + SP_OFF + (wm * 16 + lrow) * (PPITCH * 2) + lcol;
        #pragma unroll
        for (int ks = 0; ks < 4; ks++) {
            uint32_t pf[4];
            ldsm4(pf, aP0 + ks * 32);
            #pragma unroll
            for (int g = 0; g < 4; g++) {
                const uint32_t vaddr = sbase + VH_OFF + (ks * 16 + lrow) * TPITCH
                                     + (uint32_t)((wn * 64 + g * 16 + 8 * (lane >> 4)) * 2);
                uint32_t vh[4];
                ldsm4t(vh, vaddr);
                mma16816(accv[g * 2 + 0], pf, vh[0], vh[1]);
                mma16816(accv[g * 2 + 1], pf, vh[2], vh[3]);
            }
        }

        const int fr = lane >> 2;
        const int fc = (lane & 3) * 2;
        const int r0 = wm * 16 + fr;
        #pragma unroll
        for (int nt = 0; nt < 8; nt++) {
            const int col = ch * 128 + wn * 64 + (nt >> 1) * 16 + (nt & 1) * 8 + fc;
            if (r0 < SEQ)
                *reinterpret_cast<float2*>(&out[(base + r0) * DIMC + col]) =
                    make_float2(accv[nt][0], accv[nt][1]);
            if (r0 + 8 < SEQ)
                *reinterpret_cast<float2*>(&out[(base + r0 + 8) * DIMC + col]) =
                    make_float2(accv[nt][2], accv[nt][3]);
        }
    }
    #undef STAGE_TILE
}

// ---------------------------------------------------------------------------
extern "C" void kernel_launch(void* const* d_in, const int* in_sizes, int n_in,
                              void* d_out, int out_size)
{
    const float* x    = (const float*)d_in[0];
    // d_in[1] = x_all : unused by the reference
    const float* W    = (const float*)d_in[2];
    const float* bias = (const float*)d_in[3];
    float* out        = (float*)d_out;

    cudaFuncSetAttribute(z_gemm_mma,
                         cudaFuncAttributeMaxDynamicSharedMemorySize, GEMM_SMEM);
    cudaFuncSetAttribute(attn_kernel,
                         cudaFuncAttributeMaxDynamicSharedMemorySize, ATTN_SMEM_BYTES);
    cudaFuncSetAttribute(attn_kernel,
                         cudaFuncAttributePreferredSharedMemoryCarveout, 100);

    prep_w2_kernel<<<2, 256>>>(W, bias);
    convert_x_kernel<<<(M_TOTAL * (DIMC / 4)) / 256, 256>>>(x);   // 50176 blocks
    prep_M_kernel<<<dim3(8, 8), 256>>>(W);
    prep_v_kernel<<<(DIMC * DIMC) / 256, 256>>>(W);               // 1024 blocks

    dim3 gemm_grid(1024 / 128, M_TOTAL / 128);                    // 8 x 784
    z_gemm_mma<<<gemm_grid, 256, GEMM_SMEM>>>(bias);

    attn_kernel<<<NWIN, 256, ATTN_SMEM_BYTES>>>(out);
}

// round 13
// speedup vs baseline: 7.0627x; 1.0447x over previous
#include <cuda_runtime.h>
#include <cuda_fp16.h>
#include <cstdint>
#include <math.h>

// Problem constants
#define DIMC     512
#define M_TOTAL  100352      // 8*256*49
#define SEQ      49
#define NWIN     2048        // 8*256
#define SCALEQ   0.17677669529663687f   // 32^-0.5

// Scratch (__device__ globals)
__device__ __half g_Ah [(size_t)M_TOTAL * DIMC];   // xh : GEMM A operand AND attn K-hi
__device__ __half g_Al [(size_t)M_TOTAL * DIMC];   // xl : attn K-lo
__device__ __half g_Yh [(size_t)M_TOTAL * DIMC];   // Y hi  (Q)
__device__ __half g_Vh [(size_t)M_TOTAL * DIMC];   // v (+bias) fp16
__device__ __half g_Bh [(size_t)1024 * DIMC];      // GEMM B rows: n<512 -> M'[:,n], else Wv
__device__ float  g_t2 [M_TOTAL];
__device__ float  g_w2 [DIMC];

// ---------------------------------------------------------------------------
// Helpers
// ---------------------------------------------------------------------------
__device__ __forceinline__ uint32_t smem_u32(const void* p) {
    uint32_t a;
    asm("{ .reg .u64 t; cvta.to.shared.u64 t, %1; cvt.u32.u64 %0, t; }" : "=r"(a) : "l"(p));
    return a;
}
__device__ __forceinline__ void cp16(uint32_t s, const void* g) {
    asm volatile("cp.async.cg.shared.global [%0], [%1], 16;" :: "r"(s), "l"(g));
}
__device__ __forceinline__ void ldsm4(uint32_t* r, uint32_t addr) {
    asm volatile("ldmatrix.sync.aligned.m8n8.x4.shared.b16 {%0,%1,%2,%3}, [%4];"
        : "=r"(r[0]), "=r"(r[1]), "=r"(r[2]), "=r"(r[3]) : "r"(addr));
}
__device__ __forceinline__ void ldsm4t(uint32_t* r, uint32_t addr) {
    asm volatile("ldmatrix.sync.aligned.m8n8.x4.trans.shared.b16 {%0,%1,%2,%3}, [%4];"
        : "=r"(r[0]), "=r"(r[1]), "=r"(r[2]), "=r"(r[3]) : "r"(addr));
}
__device__ __forceinline__ void mma16816(float* d, const uint32_t* a, uint32_t b0, uint32_t b1) {
    asm volatile("mma.sync.aligned.m16n8k16.row.col.f32.f16.f16.f32 "
        "{%0,%1,%2,%3}, {%4,%5,%6,%7}, {%8,%9}, {%0,%1,%2,%3};"
        : "+f"(d[0]), "+f"(d[1]), "+f"(d[2]), "+f"(d[3])
        : "r"(a[0]), "r"(a[1]), "r"(a[2]), "r"(a[3]), "r"(b0), "r"(b1));
}

// ---------------------------------------------------------------------------
// prep_w2: g_w2[c] = SCALE * sum_a W[c][512+a] * bias[a]
// ---------------------------------------------------------------------------
__global__ __launch_bounds__(256)
void prep_w2_kernel(const float* __restrict__ W, const float* __restrict__ bias)
{
    int c = blockIdx.x * 256 + threadIdx.x;
    const float* row = W + (size_t)c * 1536 + 512;
    float s = 0.0f;
    for (int a = 0; a < DIMC; a++) s += row[a] * bias[a];
    g_w2[c] = SCALEQ * s;
}

// ---------------------------------------------------------------------------
// convert_x: x -> g_Ah (hi) + g_Al (lo); g_t2[m] = x_m . g_w2
// ---------------------------------------------------------------------------
__global__ __launch_bounds__(256)
void convert_x_kernel(const float* __restrict__ x)
{
    __shared__ float red[2][4];
    const int tid = threadIdx.x;
    size_t i4 = (size_t)blockIdx.x * 256 + tid;
    float4 v = reinterpret_cast<const float4*>(x)[i4];
    const int kq = (int)(i4 & 127);

    __half2 h0 = __floats2half2_rn(v.x, v.y);
    __half2 h1 = __floats2half2_rn(v.z, v.w);
    __half2 l0 = __floats2half2_rn(v.x - __low2float(h0), v.y - __high2float(h0));
    __half2 l1 = __floats2half2_rn(v.z - __low2float(h1), v.w - __high2float(h1));
    uint2 uh, ul;
    uh.x = *reinterpret_cast<uint32_t*>(&h0);
    uh.y = *reinterpret_cast<uint32_t*>(&h1);
    ul.x = *reinterpret_cast<uint32_t*>(&l0);
    ul.y = *reinterpret_cast<uint32_t*>(&l1);
    *reinterpret_cast<uint2*>(g_Ah + i4 * 4) = uh;
    *reinterpret_cast<uint2*>(g_Al + i4 * 4) = ul;

    float4 wv = *reinterpret_cast<const float4*>(&g_w2[kq * 4]);
    float p = v.x * wv.x + v.y * wv.y + v.z * wv.z + v.w * wv.w;
    #pragma unroll
    for (int o = 16; o > 0; o >>= 1) p += __shfl_down_sync(0xFFFFFFFFu, p, o);
    const int w = tid >> 5;
    if ((tid & 31) == 0) red[w >> 2][w & 3] = p;
    __syncthreads();
    if ((tid & 127) == 0) {
        const int r = tid >> 7;
        g_t2[blockIdx.x * 2 + r] = red[r][0] + red[r][1] + red[r][2] + red[r][3];
    }
}

// ---------------------------------------------------------------------------
// prep_M: M'[c1][c2] = SCALE * sum_a W[c1][a] * W[c2][512+a]
// ---------------------------------------------------------------------------
__global__ __launch_bounds__(256)
void prep_M_kernel(const float* __restrict__ W)
{
    __shared__ float sQ[16][68];
    __shared__ float sK[16][68];
    const int tid = threadIdx.x;
    const int tx = tid & 15, ty = tid >> 4;
    const int c1b = blockIdx.y * 64;
    const int c2b = blockIdx.x * 64;

    const int r  = tid >> 2;
    const int aq = (tid & 3) * 4;

    float acc[4][4];
    #pragma unroll
    for (int i = 0; i < 4; i++)
        #pragma unroll
        for (int j = 0; j < 4; j++) acc[i][j] = 0.0f;

    for (int a0 = 0; a0 < DIMC; a0 += 16) {
        __syncthreads();
        float4 wq = *reinterpret_cast<const float4*>(&W[(size_t)(c1b + r) * 1536 + a0 + aq]);
        float4 wk = *reinterpret_cast<const float4*>(&W[(size_t)(c2b + r) * 1536 + 512 + a0 + aq]);
        sQ[aq + 0][r] = wq.x; sQ[aq + 1][r] = wq.y; sQ[aq + 2][r] = wq.z; sQ[aq + 3][r] = wq.w;
        sK[aq + 0][r] = wk.x; sK[aq + 1][r] = wk.y; sK[aq + 2][r] = wk.z; sK[aq + 3][r] = wk.w;
        __syncthreads();

        #pragma unroll
        for (int a = 0; a < 16; a++) {
            float4 q = *reinterpret_cast<const float4*>(&sQ[a][ty * 4]);
            float4 k = *reinterpret_cast<const float4*>(&sK[a][tx * 4]);
            float qa[4] = {q.x, q.y, q.z, q.w};
            float ka[4] = {k.x, k.y, k.z, k.w};
            #pragma unroll
            for (int i = 0; i < 4; i++)
                #pragma unroll
                for (int j = 0; j < 4; j++)
                    acc[i][j] = fmaf(qa[i], ka[j], acc[i][j]);
        }
    }

    #pragma unroll
    for (int j = 0; j < 4; j++) {
        const int c2 = c2b + tx * 4 + j;
        #pragma unroll
        for (int i = 0; i < 4; i++) {
            const int c1 = c1b + ty * 4 + i;
            g_Bh[(size_t)c2 * DIMC + c1] = __float2half_rn(SCALEQ * acc[i][j]);
        }
    }
}

// prep_v: g_Bh[(512+nv)*512 + c] = fp16(W[c][1024+nv])
__global__ __launch_bounds__(256)
void prep_v_kernel(const float* __restrict__ W)
{
    int idx = blockIdx.x * 256 + threadIdx.x;
    int c  = idx >> 9;
    int nv = idx & 511;
    g_Bh[(size_t)(512 + nv) * DIMC + c] = __float2half_rn(W[(size_t)c * 1536 + 1024 + nv]);
}

// ---------------------------------------------------------------------------
// HMMA GEMM: [Y | v] = Ah[M,512] x Bh[N,512]^T; epilogue -> fp16 stores
//   Y half -> g_Yh (hi only);  v half -> (+bias) g_Vh
// ---------------------------------------------------------------------------
#define ROWB         80
#define TILE_BYTES_G (128 * ROWB)
#define STAGE_BYTES  (2 * TILE_BYTES_G)
#define GEMM_SMEM    (3 * STAGE_BYTES)
#define NCHUNK       (DIMC / 32)

__global__ __launch_bounds__(256, 2)
void z_gemm_mma(const float* __restrict__ bias)
{
    extern __shared__ char sbuf[];
    const uint32_t sbase = smem_u32(sbuf);

    const int tid  = threadIdx.x;
    const int wid  = tid >> 5;
    const int lane = tid & 31;
    const int wm   = wid >> 1;
    const int wn   = wid & 1;
    const int bn0  = blockIdx.x * 128;
    const int bm0  = blockIdx.y * 128;

    const int rc = tid >> 2;
    const int jc = tid & 3;
    const __half* Ag = g_Ah + (size_t)(bm0 + rc) * DIMC + jc * 8;
    const __half* Bg = g_Bh + (size_t)(bn0 + rc) * DIMC + jc * 8;
    const uint32_t sA_off = (uint32_t)(rc * ROWB + jc * 16);

    float acc[2][8][4];
    #pragma unroll
    for (int mi = 0; mi < 2; mi++)
        #pragma unroll
        for (int ni = 0; ni < 8; ni++)
            #pragma unroll
            for (int t = 0; t < 4; t++) acc[mi][ni][t] = 0.0f;

    const uint32_t lrow = (uint32_t)(lane & 15);
    const uint32_t lcol = (uint32_t)((lane & 16) ? 16 : 0);

    #define ISSUE_STAGE(cc) do {                                             \
        const int _k0 = (cc) * 32;                                           \
        const uint32_t _st = sbase + ((cc) % 3) * STAGE_BYTES;               \
        cp16(_st + sA_off,                            Ag + _k0);             \
        cp16(_st + sA_off + 64 * ROWB,                Ag + (size_t)64 * DIMC + _k0); \
        cp16(_st + TILE_BYTES_G + sA_off,             Bg + _k0);             \
        cp16(_st + TILE_BYTES_G + sA_off + 64 * ROWB, Bg + (size_t)64 * DIMC + _k0); \
        asm volatile("cp.async.commit_group;" ::: "memory");                 \
    } while (0)

    ISSUE_STAGE(0);
    ISSUE_STAGE(1);

    for (int c = 0; c < NCHUNK; ++c) {
        if (c + 2 < NCHUNK) {
            asm volatile("cp.async.wait_group 1;" ::: "memory");
        } else {
            asm volatile("cp.async.wait_group 0;" ::: "memory");
        }
        __syncthreads();
        if (c + 2 < NCHUNK) ISSUE_STAGE(c + 2);

        const uint32_t sAu = sbase + (c % 3) * STAGE_BYTES;
        const uint32_t sBu = sAu + TILE_BYTES_G;
        const uint32_t aBase = sAu + (wm * 32 + lrow) * ROWB + lcol;
        const uint32_t bBase = sBu + (wn * 64 + lrow) * ROWB + lcol;

        #pragma unroll
        for (int ks = 0; ks < 2; ks++) {
            uint32_t afr[2][4];
            ldsm4(afr[0], aBase + ks * 32);
            ldsm4(afr[1], aBase + 16 * ROWB + ks * 32);
            #pragma unroll
            for (int pi = 0; pi < 4; pi++) {
                uint32_t bfr[4];
                ldsm4(bfr, bBase + pi * 16 * ROWB + ks * 32);
                mma16816(acc[0][2 * pi + 0], afr[0], bfr[0], bfr[2]);
                mma16816(acc[0][2 * pi + 1], afr[0], bfr[1], bfr[3]);
                mma16816(acc[1][2 * pi + 0], afr[1], bfr[0], bfr[2]);
                mma16816(acc[1][2 * pi + 1], afr[1], bfr[1], bfr[3]);
            }
        }
    }
    #undef ISSUE_STAGE

    // ---- epilogue
    const bool isv = (bn0 >= DIMC);
    const int r0 = bm0 + wm * 32 + (lane >> 2);
    const int c0 = bn0 + wn * 64 + (lane & 3) * 2;
    #pragma unroll
    for (int ni = 0; ni < 8; ni++) {
        const int col = c0 + ni * 8;
        float2 bb = make_float2(0.0f, 0.0f);
        if (isv) bb = *reinterpret_cast<const float2*>(&bias[512 + col]);
        #pragma unroll
        for (int mi = 0; mi < 2; mi++) {
            const int row = r0 + mi * 16;
            #pragma unroll
            for (int h = 0; h < 2; h++) {
                const float vx = acc[mi][ni][2 * h + 0] + bb.x;
                const float vy = acc[mi][ni][2 * h + 1] + bb.y;
                const size_t o = (size_t)(row + 8 * h) * DIMC + (col - (isv ? DIMC : 0));
                __half2 hh = __floats2half2_rn(vx, vy);
                if (isv) *reinterpret_cast<__half2*>(&g_Vh[o]) = hh;
                else     *reinterpret_cast<__half2*>(&g_Yh[o]) = hh;
            }
        }
    }
}

// ---------------------------------------------------------------------------
// HMMA attention. One CTA per window, 8 warps, seq padded 49->64, occ 3.
//  S = Qh*Kh + Qh*Kl    (Qh = Yh fp16; K = x hi/lo split -> near-exact K)
//  softmax (+t2) -> P fp16 (pitch 72 halves)
//  O = P*Vh
// smem: Qh@0  Kh@17408  Kl@34816  (TPITCH=272)
//       then sS fp32 @0 (64x68f = 17408 exactly), sP @17408 (64x72h=9216)
//       Vh reuses Kl region @34816;  sT2 @52224 -> total 52480
// ---------------------------------------------------------------------------
#define TPITCH   272
#define PPITCH   72
#define QH_OFF   0
#define KH_OFF   17408
#define KL_OFF   34816
#define SS_OFF   0
#define SP_OFF   17408
#define VH_OFF   34816
#define T2_OFF   52224
#define ATTN_SMEM_BYTES 52480

__global__ __launch_bounds__(256, 3)
void attn_kernel(float* __restrict__ out)
{
    extern __shared__ char smb[];
    const uint32_t sbase = smem_u32(smb);

    const int w    = blockIdx.x;
    const int tid  = threadIdx.x;
    const int wid  = tid >> 5;
    const int lane = tid & 31;
    const int wm   = wid >> 1;
    const int wn   = wid & 1;
    const size_t base = (size_t)w * SEQ;

    float* sT2 = reinterpret_cast<float*>(smb + T2_OFF);
    if (tid < SEQ) sT2[tid] = g_t2[base + tid];

    // zero pad rows 49..63 of the 3 tile regions (Vh reuses Kl, pads stay 0)
    for (int idx = tid; idx < 2880; idx += 256) {
        const int region = idx / 960;            // 0..2
        const int rem    = idx % 960;
        const uint32_t off = (uint32_t)region * 17408u;
        *reinterpret_cast<uint32_t*>(smb + off + (49 + rem / 64) * TPITCH + (rem % 64) * 4) = 0;
    }

    const uint32_t lrow = (uint32_t)(lane & 15);
    const uint32_t lcol = (uint32_t)((lane & 16) ? 16 : 0);

    #define STAGE_TILE(gp, soff) \
        for (int t = tid; t < 784; t += 256) { \
            const int row = t >> 4; const int ck = t & 15; \
            cp16(sbase + (soff) + row * TPITCH + ck * 16, \
                 (gp) + (size_t)(base + row) * DIMC + ch * 128 + ck * 8); \
        }

    float accS[4][4];
    #pragma unroll
    for (int nt = 0; nt < 4; nt++)
        #pragma unroll
        for (int t = 0; t < 4; t++) accS[nt][t] = 0.0f;

    // ================= Phase S: 4 channel chunks of 128 =================
    for (int ch = 0; ch < 4; ch++) {
        __syncthreads();
        STAGE_TILE(g_Yh, QH_OFF)
        STAGE_TILE(g_Ah, KH_OFF)
        STAGE_TILE(g_Al, KL_OFF)
        asm volatile("cp.async.commit_group;" ::: "memory");
        asm volatile("cp.async.wait_group 0;" ::: "memory");
        __syncthreads();

        const uint32_t aQh = sbase + QH_OFF + (wm * 16 + lrow) * TPITCH + lcol;
        const uint32_t bKh = sbase + KH_OFF + (wn * 32 + lrow) * TPITCH + lcol;
        const uint32_t bKl = bKh + (KL_OFF - KH_OFF);

        #pragma unroll
        for (int ks = 0; ks < 8; ks++) {
            const uint32_t off = ks * 32;
            uint32_t qh[4];
            ldsm4(qh, aQh + off);
            #pragma unroll
            for (int g = 0; g < 2; g++) {
                uint32_t kh[4], kl[4];
                ldsm4(kh, bKh + g * 16 * TPITCH + off);
                ldsm4(kl, bKl + g * 16 * TPITCH + off);
                mma16816(accS[g * 2 + 0], qh, kh[0], kh[2]);
                mma16816(accS[g * 2 + 1], qh, kh[1], kh[3]);
                mma16816(accS[g * 2 + 0], qh, kl[0], kl[2]);
                mma16816(accS[g * 2 + 1], qh, kl[1], kl[3]);
            }
        }
    }

    // ---- store S to smem (fp32, pitch 68 floats) ----
    __syncthreads();
    float* sS = reinterpret_cast<float*>(smb + SS_OFF);
    {
        const int fr = lane >> 2;
        const int fc = (lane & 3) * 2;
        #pragma unroll
        for (int nt = 0; nt < 4; nt++) {
            const int col = wn * 32 + nt * 8 + fc;
            *reinterpret_cast<float2*>(&sS[(wm * 16 + fr) * 68 + col]) =
                make_float2(accS[nt][0], accS[nt][1]);
            *reinterpret_cast<float2*>(&sS[(wm * 16 + fr + 8) * 68 + col]) =
                make_float2(accS[nt][2], accS[nt][3]);
        }
    }
    __syncthreads();

    // ---- softmax (adds t2), write P fp16 ----
    __half* sP = reinterpret_cast<__half*>(smb + SP_OFF);
    for (int r = wid; r < 64; r += 8) {
        const float* row = sS + r * 68;
        const float v0 = (lane < SEQ)      ? row[lane]      + sT2[lane]      : -1e30f;
        const float v1 = (lane + 32 < SEQ) ? row[lane + 32] + sT2[lane + 32] : -1e30f;
        float mx = fmaxf(v0, v1);
        #pragma unroll
        for (int o = 16; o > 0; o >>= 1)
            mx = fmaxf(mx, __shfl_xor_sync(0xFFFFFFFFu, mx, o));
        const float e0 = (lane < SEQ)      ? __expf(v0 - mx) : 0.0f;
        const float e1 = (lane + 32 < SEQ) ? __expf(v1 - mx) : 0.0f;
        float s = e0 + e1;
        #pragma unroll
        for (int o = 16; o > 0; o >>= 1)
            s += __shfl_xor_sync(0xFFFFFFFFu, s, o);
        const float inv = 1.0f / s;
        sP[r * PPITCH + lane]      = __float2half_rn(e0 * inv);
        sP[r * PPITCH + lane + 32] = __float2half_rn(e1 * inv);
    }

    // ================= Phase PV: 4 channel chunks of 128 =================
    for (int ch = 0; ch < 4; ch++) {
        __syncthreads();
        STAGE_TILE(g_Vh, VH_OFF)
        asm volatile("cp.async.commit_group;" ::: "memory");
        asm volatile("cp.async.wait_group 0;" ::: "memory");
        __syncthreads();

        float accv[8][4];
        #pragma unroll
        for (int nt = 0; nt < 8; nt++)
            #pragma unroll
            for (int t = 0; t < 4; t++) accv[nt][t] = 0.0f;

        const uint32_t aP0 = sbase + SP_OFF + (wm * 16 + lrow) * (PPITCH * 2) + lcol;
        #pragma unroll
        for (int ks = 0; ks < 4; ks++) {
            uint32_t pf[4];
            ldsm4(pf, aP0 + ks * 32);
            #pragma unroll
            for (int g = 0; g < 4; g++) {
                const uint32_t vaddr = sbase + VH_OFF + (ks * 16 + lrow) * TPITCH
                                     + (uint32_t)((wn * 64 + g * 16 + 8 * (lane >> 4)) * 2);
                uint32_t vh[4];
                ldsm4t(vh, vaddr);
                mma16816(accv[g * 2 + 0], pf, vh[0], vh[1]);
                mma16816(accv[g * 2 + 1], pf, vh[2], vh[3]);
            }
        }

        const int fr = lane >> 2;
        const int fc = (lane & 3) * 2;
        const int r0 = wm * 16 + fr;
        #pragma unroll
        for (int nt = 0; nt < 8; nt++) {
            const int col = ch * 128 + wn * 64 + (nt >> 1) * 16 + (nt & 1) * 8 + fc;
            if (r0 < SEQ)
                *reinterpret_cast<float2*>(&out[(base + r0) * DIMC + col]) =
                    make_float2(accv[nt][0], accv[nt][1]);
            if (r0 + 8 < SEQ)
                *reinterpret_cast<float2*>(&out[(base + r0 + 8) * DIMC + col]) =
                    make_float2(accv[nt][2], accv[nt][3]);
        }
    }
    #undef STAGE_TILE
}

// ---------------------------------------------------------------------------
extern "C" void kernel_launch(void* const* d_in, const int* in_sizes, int n_in,
                              void* d_out, int out_size)
{
    const float* x    = (const float*)d_in[0];
    // d_in[1] = x_all : unused by the reference
    const float* W    = (const float*)d_in[2];
    const float* bias = (const float*)d_in[3];
    float* out        = (float*)d_out;

    cudaFuncSetAttribute(z_gemm_mma,
                         cudaFuncAttributeMaxDynamicSharedMemorySize, GEMM_SMEM);
    cudaFuncSetAttribute(attn_kernel,
                         cudaFuncAttributeMaxDynamicSharedMemorySize, ATTN_SMEM_BYTES);
    cudaFuncSetAttribute(attn_kernel,
                         cudaFuncAttributePreferredSharedMemoryCarveout, 100);

    prep_w2_kernel<<<2, 256>>>(W, bias);
    convert_x_kernel<<<(M_TOTAL * (DIMC / 4)) / 256, 256>>>(x);   // 50176 blocks
    prep_M_kernel<<<dim3(8, 8), 256>>>(W);
    prep_v_kernel<<<(DIMC * DIMC) / 256, 256>>>(W);               // 1024 blocks

    dim3 gemm_grid(1024 / 128, M_TOTAL / 128);                    // 8 x 784
    z_gemm_mma<<<gemm_grid, 256, GEMM_SMEM>>>(bias);

    attn_kernel<<<NWIN, 256, ATTN_SMEM_BYTES>>>(out);
}

// round 14
// speedup vs baseline: 7.1774x; 1.0162x over previous
#include <cuda_runtime.h>
#include <cuda_fp16.h>
#include <cstdint>
#include <math.h>

// Problem constants
#define DIMC     512
#define M_TOTAL  100352      // 8*256*49
#define SEQ      49
#define NWIN     2048        // 8*256
#define SCALEQ   0.17677669529663687f   // 32^-0.5

// Scratch (__device__ globals)
__device__ __half g_Ah [(size_t)M_TOTAL * DIMC];   // xh : GEMM A operand AND attn K-hi
__device__ __half g_Al [(size_t)M_TOTAL * DIMC];   // xl : attn K-lo
__device__ __half g_Yh [(size_t)M_TOTAL * DIMC];   // Y hi  (Q)
__device__ __half g_Vh [(size_t)M_TOTAL * DIMC];   // v (+bias) fp16
__device__ __half g_Bh [(size_t)1024 * DIMC];      // GEMM B rows: n<512 -> M'[:,n], else Wv
__device__ float  g_t2 [M_TOTAL];
__device__ float  g_w2 [DIMC];

// ---------------------------------------------------------------------------
// Helpers
// ---------------------------------------------------------------------------
__device__ __forceinline__ uint32_t smem_u32(const void* p) {
    uint32_t a;
    asm("{ .reg .u64 t; cvta.to.shared.u64 t, %1; cvt.u32.u64 %0, t; }" : "=r"(a) : "l"(p));
    return a;
}
__device__ __forceinline__ void cp16(uint32_t s, const void* g) {
    asm volatile("cp.async.cg.shared.global [%0], [%1], 16;" :: "r"(s), "l"(g));
}
__device__ __forceinline__ void ldsm4(uint32_t* r, uint32_t addr) {
    asm volatile("ldmatrix.sync.aligned.m8n8.x4.shared.b16 {%0,%1,%2,%3}, [%4];"
        : "=r"(r[0]), "=r"(r[1]), "=r"(r[2]), "=r"(r[3]) : "r"(addr));
}
__device__ __forceinline__ void ldsm4t(uint32_t* r, uint32_t addr) {
    asm volatile("ldmatrix.sync.aligned.m8n8.x4.trans.shared.b16 {%0,%1,%2,%3}, [%4];"
        : "=r"(r[0]), "=r"(r[1]), "=r"(r[2]), "=r"(r[3]) : "r"(addr));
}
__device__ __forceinline__ void mma16816(float* d, const uint32_t* a, uint32_t b0, uint32_t b1) {
    asm volatile("mma.sync.aligned.m16n8k16.row.col.f32.f16.f16.f32 "
        "{%0,%1,%2,%3}, {%4,%5,%6,%7}, {%8,%9}, {%0,%1,%2,%3};"
        : "+f"(d[0]), "+f"(d[1]), "+f"(d[2]), "+f"(d[3])
        : "r"(a[0]), "r"(a[1]), "r"(a[2]), "r"(a[3]), "r"(b0), "r"(b1));
}

// ---------------------------------------------------------------------------
// prep_w2: g_w2[c] = SCALE * sum_a W[c][512+a] * bias[a]
// ---------------------------------------------------------------------------
__global__ __launch_bounds__(256)
void prep_w2_kernel(const float* __restrict__ W, const float* __restrict__ bias)
{
    int c = blockIdx.x * 256 + threadIdx.x;
    const float* row = W + (size_t)c * 1536 + 512;
    float s = 0.0f;
    for (int a = 0; a < DIMC; a++) s += row[a] * bias[a];
    g_w2[c] = SCALEQ * s;
}

// ---------------------------------------------------------------------------
// convert_x: x -> g_Ah (hi) + g_Al (lo); g_t2[m] = x_m . g_w2
// ---------------------------------------------------------------------------
__global__ __launch_bounds__(256)
void convert_x_kernel(const float* __restrict__ x)
{
    __shared__ float red[2][4];
    const int tid = threadIdx.x;
    size_t i4 = (size_t)blockIdx.x * 256 + tid;
    float4 v = reinterpret_cast<const float4*>(x)[i4];
    const int kq = (int)(i4 & 127);

    __half2 h0 = __floats2half2_rn(v.x, v.y);
    __half2 h1 = __floats2half2_rn(v.z, v.w);
    __half2 l0 = __floats2half2_rn(v.x - __low2float(h0), v.y - __high2float(h0));
    __half2 l1 = __floats2half2_rn(v.z - __low2float(h1), v.w - __high2float(h1));
    uint2 uh, ul;
    uh.x = *reinterpret_cast<uint32_t*>(&h0);
    uh.y = *reinterpret_cast<uint32_t*>(&h1);
    ul.x = *reinterpret_cast<uint32_t*>(&l0);
    ul.y = *reinterpret_cast<uint32_t*>(&l1);
    *reinterpret_cast<uint2*>(g_Ah + i4 * 4) = uh;
    *reinterpret_cast<uint2*>(g_Al + i4 * 4) = ul;

    float4 wv = *reinterpret_cast<const float4*>(&g_w2[kq * 4]);
    float p = v.x * wv.x + v.y * wv.y + v.z * wv.z + v.w * wv.w;
    #pragma unroll
    for (int o = 16; o > 0; o >>= 1) p += __shfl_down_sync(0xFFFFFFFFu, p, o);
    const int w = tid >> 5;
    if ((tid & 31) == 0) red[w >> 2][w & 3] = p;
    __syncthreads();
    if ((tid & 127) == 0) {
        const int r = tid >> 7;
        g_t2[blockIdx.x * 2 + r] = red[r][0] + red[r][1] + red[r][2] + red[r][3];
    }
}

// ---------------------------------------------------------------------------
// prep_M: M'[c1][c2] = SCALE * sum_a W[c1][a] * W[c2][512+a]
// ---------------------------------------------------------------------------
__global__ __launch_bounds__(256)
void prep_M_kernel(const float* __restrict__ W)
{
    __shared__ float sQ[16][68];
    __shared__ float sK[16][68];
    const int tid = threadIdx.x;
    const int tx = tid & 15, ty = tid >> 4;
    const int c1b = blockIdx.y * 64;
    const int c2b = blockIdx.x * 64;

    const int r  = tid >> 2;
    const int aq = (tid & 3) * 4;

    float acc[4][4];
    #pragma unroll
    for (int i = 0; i < 4; i++)
        #pragma unroll
        for (int j = 0; j < 4; j++) acc[i][j] = 0.0f;

    for (int a0 = 0; a0 < DIMC; a0 += 16) {
        __syncthreads();
        float4 wq = *reinterpret_cast<const float4*>(&W[(size_t)(c1b + r) * 1536 + a0 + aq]);
        float4 wk = *reinterpret_cast<const float4*>(&W[(size_t)(c2b + r) * 1536 + 512 + a0 + aq]);
        sQ[aq + 0][r] = wq.x; sQ[aq + 1][r] = wq.y; sQ[aq + 2][r] = wq.z; sQ[aq + 3][r] = wq.w;
        sK[aq + 0][r] = wk.x; sK[aq + 1][r] = wk.y; sK[aq + 2][r] = wk.z; sK[aq + 3][r] = wk.w;
        __syncthreads();

        #pragma unroll
        for (int a = 0; a < 16; a++) {
            float4 q = *reinterpret_cast<const float4*>(&sQ[a][ty * 4]);
            float4 k = *reinterpret_cast<const float4*>(&sK[a][tx * 4]);
            float qa[4] = {q.x, q.y, q.z, q.w};
            float ka[4] = {k.x, k.y, k.z, k.w};
            #pragma unroll
            for (int i = 0; i < 4; i++)
                #pragma unroll
                for (int j = 0; j < 4; j++)
                    acc[i][j] = fmaf(qa[i], ka[j], acc[i][j]);
        }
    }

    #pragma unroll
    for (int j = 0; j < 4; j++) {
        const int c2 = c2b + tx * 4 + j;
        #pragma unroll
        for (int i = 0; i < 4; i++) {
            const int c1 = c1b + ty * 4 + i;
            g_Bh[(size_t)c2 * DIMC + c1] = __float2half_rn(SCALEQ * acc[i][j]);
        }
    }
}

// prep_v: g_Bh[(512+nv)*512 + c] = fp16(W[c][1024+nv])
__global__ __launch_bounds__(256)
void prep_v_kernel(const float* __restrict__ W)
{
    int idx = blockIdx.x * 256 + threadIdx.x;
    int c  = idx >> 9;
    int nv = idx & 511;
    g_Bh[(size_t)(512 + nv) * DIMC + c] = __float2half_rn(W[(size_t)c * 1536 + 1024 + nv]);
}

// ---------------------------------------------------------------------------
// HMMA GEMM: [Y | v] = Ah[M,512] x Bh[N,512]^T; epilogue -> fp16 stores
// ---------------------------------------------------------------------------
#define ROWB         80
#define TILE_BYTES_G (128 * ROWB)
#define STAGE_BYTES  (2 * TILE_BYTES_G)
#define GEMM_SMEM    (3 * STAGE_BYTES)
#define NCHUNK       (DIMC / 32)

__global__ __launch_bounds__(256, 2)
void z_gemm_mma(const float* __restrict__ bias)
{
    extern __shared__ char sbuf[];
    const uint32_t sbase = smem_u32(sbuf);

    const int tid  = threadIdx.x;
    const int wid  = tid >> 5;
    const int lane = tid & 31;
    const int wm   = wid >> 1;
    const int wn   = wid & 1;
    const int bn0  = blockIdx.x * 128;
    const int bm0  = blockIdx.y * 128;

    const int rc = tid >> 2;
    const int jc = tid & 3;
    const __half* Ag = g_Ah + (size_t)(bm0 + rc) * DIMC + jc * 8;
    const __half* Bg = g_Bh + (size_t)(bn0 + rc) * DIMC + jc * 8;
    const uint32_t sA_off = (uint32_t)(rc * ROWB + jc * 16);

    float acc[2][8][4];
    #pragma unroll
    for (int mi = 0; mi < 2; mi++)
        #pragma unroll
        for (int ni = 0; ni < 8; ni++)
            #pragma unroll
            for (int t = 0; t < 4; t++) acc[mi][ni][t] = 0.0f;

    const uint32_t lrow = (uint32_t)(lane & 15);
    const uint32_t lcol = (uint32_t)((lane & 16) ? 16 : 0);

    #define ISSUE_STAGE(cc) do {                                             \
        const int _k0 = (cc) * 32;                                           \
        const uint32_t _st = sbase + ((cc) % 3) * STAGE_BYTES;               \
        cp16(_st + sA_off,                            Ag + _k0);             \
        cp16(_st + sA_off + 64 * ROWB,                Ag + (size_t)64 * DIMC + _k0); \
        cp16(_st + TILE_BYTES_G + sA_off,             Bg + _k0);             \
        cp16(_st + TILE_BYTES_G + sA_off + 64 * ROWB, Bg + (size_t)64 * DIMC + _k0); \
        asm volatile("cp.async.commit_group;" ::: "memory");                 \
    } while (0)

    ISSUE_STAGE(0);
    ISSUE_STAGE(1);

    for (int c = 0; c < NCHUNK; ++c) {
        if (c + 2 < NCHUNK) {
            asm volatile("cp.async.wait_group 1;" ::: "memory");
        } else {
            asm volatile("cp.async.wait_group 0;" ::: "memory");
        }
        __syncthreads();
        if (c + 2 < NCHUNK) ISSUE_STAGE(c + 2);

        const uint32_t sAu = sbase + (c % 3) * STAGE_BYTES;
        const uint32_t sBu = sAu + TILE_BYTES_G;
        const uint32_t aBase = sAu + (wm * 32 + lrow) * ROWB + lcol;
        const uint32_t bBase = sBu + (wn * 64 + lrow) * ROWB + lcol;

        #pragma unroll
        for (int ks = 0; ks < 2; ks++) {
            uint32_t afr[2][4];
            ldsm4(afr[0], aBase + ks * 32);
            ldsm4(afr[1], aBase + 16 * ROWB + ks * 32);
            #pragma unroll
            for (int pi = 0; pi < 4; pi++) {
                uint32_t bfr[4];
                ldsm4(bfr, bBase + pi * 16 * ROWB + ks * 32);
                mma16816(acc[0][2 * pi + 0], afr[0], bfr[0], bfr[2]);
                mma16816(acc[0][2 * pi + 1], afr[0], bfr[1], bfr[3]);
                mma16816(acc[1][2 * pi + 0], afr[1], bfr[0], bfr[2]);
                mma16816(acc[1][2 * pi + 1], afr[1], bfr[1], bfr[3]);
            }
        }
    }
    #undef ISSUE_STAGE

    // ---- epilogue
    const bool isv = (bn0 >= DIMC);
    const int r0 = bm0 + wm * 32 + (lane >> 2);
    const int c0 = bn0 + wn * 64 + (lane & 3) * 2;
    #pragma unroll
    for (int ni = 0; ni < 8; ni++) {
        const int col = c0 + ni * 8;
        float2 bb = make_float2(0.0f, 0.0f);
        if (isv) bb = *reinterpret_cast<const float2*>(&bias[512 + col]);
        #pragma unroll
        for (int mi = 0; mi < 2; mi++) {
            const int row = r0 + mi * 16;
            #pragma unroll
            for (int h = 0; h < 2; h++) {
                const float vx = acc[mi][ni][2 * h + 0] + bb.x;
                const float vy = acc[mi][ni][2 * h + 1] + bb.y;
                const size_t o = (size_t)(row + 8 * h) * DIMC + (col - (isv ? DIMC : 0));
                __half2 hh = __floats2half2_rn(vx, vy);
                if (isv) *reinterpret_cast<__half2*>(&g_Vh[o]) = hh;
                else     *reinterpret_cast<__half2*>(&g_Yh[o]) = hh;
            }
        }
    }
}

// ---------------------------------------------------------------------------
// HMMA attention, fully double-buffered. One CTA/window, 8 warps, occ 3.
// 8 chunks of 64 channels; region = 64 rows x 144 B (pitch 16-B aligned,
// same mod-128 bank walk as the proven 272 pitch).
//  S = Qh*(Kh + Kl)  accumulated over chunks; softmax(+t2) -> P fp16; O = P*Vh
// smem layout (bytes):
//  S phase : QH0@0 QH1@9216 KH0@18432 KH1@27648 KL0@36864 KL1@46080
//  after   : sS fp32 @0 (64x68f = 17408), sP @18432 (64x72h = 9216)
//            V double-buffer @36864 / @46080 (dead KL regions)
//  sT2 @55296 -> total 55552
// ---------------------------------------------------------------------------
#define CPITCH   144
#define PPITCH   72
#define REG      9216
#define QH0_OFF  0
#define KH0_OFF  18432
#define KL0_OFF  36864
#define SS_OFF   0
#define SP_OFF   18432
#define VB0_OFF  36864
#define VB1_OFF  46080
#define T2_OFF   55296
#define ATTN_SMEM_BYTES 55552

__global__ __launch_bounds__(256, 3)
void attn_kernel(float* __restrict__ out)
{
    extern __shared__ char smb[];
    const uint32_t sbase = smem_u32(smb);

    const int w    = blockIdx.x;
    const int tid  = threadIdx.x;
    const int wid  = tid >> 5;
    const int lane = tid & 31;
    const int wm   = wid >> 1;          // row tile (16 rows)
    const int wn   = wid & 1;           // col half (32 cols)
    const size_t base = (size_t)w * SEQ;

    float* sT2 = reinterpret_cast<float*>(smb + T2_OFF);
    if (tid < SEQ) sT2[tid] = g_t2[base + tid];

    // zero pad rows 49..63 of all 6 regions (V reuses KL -> pads stay zero)
    for (int idx = tid; idx < 2880; idx += 256) {
        const int region = idx / 480;
        const int rem    = idx % 480;
        *reinterpret_cast<uint32_t*>(smb + region * REG +
            (49 + rem / 32) * CPITCH + (rem % 32) * 4) = 0;
    }

    const uint32_t lrow = (uint32_t)(lane & 15);
    const uint32_t lcol = (uint32_t)((lane & 16) ? 16 : 0);

    // one 64-channel tile: 49 rows x 128 B
    #define STAGE64(gp, soff, cc) \
        for (int t = tid; t < 392; t += 256) { \
            const int row = t >> 3; const int ck = t & 7; \
            cp16(sbase + (soff) + row * CPITCH + ck * 16, \
                 (gp) + (size_t)(base + row) * DIMC + (cc) * 64 + ck * 8); \
        }
    #define STAGE_S(cc, b) do { \
        STAGE64(g_Yh, QH0_OFF + (b) * REG, cc) \
        STAGE64(g_Ah, KH0_OFF + (b) * REG, cc) \
        STAGE64(g_Al, KL0_OFF + (b) * REG, cc) \
        asm volatile("cp.async.commit_group;" ::: "memory"); \
    } while (0)

    float accS[4][4];
    #pragma unroll
    for (int nt = 0; nt < 4; nt++)
        #pragma unroll
        for (int t = 0; t < 4; t++) accS[nt][t] = 0.0f;

    STAGE_S(0, 0);
    STAGE_S(1, 1);

    // ================= Phase S: 8 chunks, 2-deep pipeline =================
    for (int ch = 0; ch < 8; ch++) {
        if (ch < 7) asm volatile("cp.async.wait_group 1;" ::: "memory");
        else        asm volatile("cp.async.wait_group 0;" ::: "memory");
        __syncthreads();

        const int b = ch & 1;
        const uint32_t aQh = sbase + QH0_OFF + b * REG + (wm * 16 + lrow) * CPITCH + lcol;
        const uint32_t bKh = sbase + KH0_OFF + b * REG + (wn * 32 + lrow) * CPITCH + lcol;
        const uint32_t bKl = bKh + (KL0_OFF - KH0_OFF);

        #pragma unroll
        for (int ks = 0; ks < 4; ks++) {
            const uint32_t off = ks * 32;
            uint32_t qh[4];
            ldsm4(qh, aQh + off);
            #pragma unroll
            for (int g = 0; g < 2; g++) {
                uint32_t kh[4], kl[4];
                ldsm4(kh, bKh + g * 16 * CPITCH + off);
                ldsm4(kl, bKl + g * 16 * CPITCH + off);
                mma16816(accS[g * 2 + 0], qh, kh[0], kh[2]);
                mma16816(accS[g * 2 + 1], qh, kh[1], kh[3]);
                mma16816(accS[g * 2 + 0], qh, kl[0], kl[2]);
                mma16816(accS[g * 2 + 1], qh, kl[1], kl[3]);
            }
        }
        __syncthreads();
        if (ch + 2 < 8) STAGE_S(ch + 2, ch & 1);
    }

    // ---- prefetch V chunk 0 (KL0 region dead), store S, softmax ----
    STAGE64(g_Vh, VB0_OFF, 0)
    asm volatile("cp.async.commit_group;" ::: "memory");

    float* sS = reinterpret_cast<float*>(smb + SS_OFF);
    {
        const int fr = lane >> 2;
        const int fc = (lane & 3) * 2;
        #pragma unroll
        for (int nt = 0; nt < 4; nt++) {
            const int col = wn * 32 + nt * 8 + fc;
            *reinterpret_cast<float2*>(&sS[(wm * 16 + fr) * 68 + col]) =
                make_float2(accS[nt][0], accS[nt][1]);
            *reinterpret_cast<float2*>(&sS[(wm * 16 + fr + 8) * 68 + col]) =
                make_float2(accS[nt][2], accS[nt][3]);
        }
    }
    __syncthreads();

    __half* sP = reinterpret_cast<__half*>(smb + SP_OFF);
    for (int r = wid; r < 64; r += 8) {
        const float* row = sS + r * 68;
        const float v0 = (lane < SEQ)      ? row[lane]      + sT2[lane]      : -1e30f;
        const float v1 = (lane + 32 < SEQ) ? row[lane + 32] + sT2[lane + 32] : -1e30f;
        float mx = fmaxf(v0, v1);
        #pragma unroll
        for (int o = 16; o > 0; o >>= 1)
            mx = fmaxf(mx, __shfl_xor_sync(0xFFFFFFFFu, mx, o));
        const float e0 = (lane < SEQ)      ? __expf(v0 - mx) : 0.0f;
        const float e1 = (lane + 32 < SEQ) ? __expf(v1 - mx) : 0.0f;
        float s = e0 + e1;
        #pragma unroll
        for (int o = 16; o > 0; o >>= 1)
            s += __shfl_xor_sync(0xFFFFFFFFu, s, o);
        const float inv = 1.0f / s;
        sP[r * PPITCH + lane]      = __float2half_rn(e0 * inv);
        sP[r * PPITCH + lane + 32] = __float2half_rn(e1 * inv);
    }
    __syncthreads();

    STAGE64(g_Vh, VB1_OFF, 1)
    asm volatile("cp.async.commit_group;" ::: "memory");

    // ================= Phase PV: 8 chunks, 2-deep pipeline =================
    const int fr = lane >> 2;
    const int fc = (lane & 3) * 2;
    const int r0 = wm * 16 + fr;
    const uint32_t aP0 = sbase + SP_OFF + (wm * 16 + lrow) * (PPITCH * 2) + lcol;

    for (int ch = 0; ch < 8; ch++) {
        if (ch < 7) asm volatile("cp.async.wait_group 1;" ::: "memory");
        else        asm volatile("cp.async.wait_group 0;" ::: "memory");
        __syncthreads();

        const uint32_t vbuf = sbase + ((ch & 1) ? VB1_OFF : VB0_OFF);

        float accv[4][4];
        #pragma unroll
        for (int nt = 0; nt < 4; nt++)
            #pragma unroll
            for (int t = 0; t < 4; t++) accv[nt][t] = 0.0f;

        #pragma unroll
        for (int ks = 0; ks < 4; ks++) {
            uint32_t pf[4];
            ldsm4(pf, aP0 + ks * 32);
            #pragma unroll
            for (int g = 0; g < 2; g++) {
                const uint32_t vaddr = vbuf + (ks * 16 + lrow) * CPITCH
                                     + (uint32_t)((wn * 32 + g * 16 + 8 * (lane >> 4)) * 2);
                uint32_t vh[4];
                ldsm4t(vh, vaddr);
                mma16816(accv[g * 2 + 0], pf, vh[0], vh[1]);
                mma16816(accv[g * 2 + 1], pf, vh[2], vh[3]);
            }
        }

        #pragma unroll
        for (int nt = 0; nt < 4; nt++) {
            const int col = ch * 64 + wn * 32 + (nt >> 1) * 16 + (nt & 1) * 8 + fc;
            if (r0 < SEQ)
                *reinterpret_cast<float2*>(&out[(base + r0) * DIMC + col]) =
                    make_float2(accv[nt][0], accv[nt][1]);
            if (r0 + 8 < SEQ)
                *reinterpret_cast<float2*>(&out[(base + r0 + 8) * DIMC + col]) =
                    make_float2(accv[nt][2], accv[nt][3]);
        }
        __syncthreads();
        if (ch + 2 < 8) {
            const uint32_t voff = (ch & 1) ? VB1_OFF : VB0_OFF;
            STAGE64(g_Vh, voff, ch + 2)
            asm volatile("cp.async.commit_group;" ::: "memory");
        }
    }
    #undef STAGE64
    #undef STAGE_S
}

// ---------------------------------------------------------------------------
extern "C" void kernel_launch(void* const* d_in, const int* in_sizes, int n_in,
                              void* d_out, int out_size)
{
    const float* x    = (const float*)d_in[0];
    // d_in[1] = x_all : unused by the reference
    const float* W    = (const float*)d_in[2];
    const float* bias = (const float*)d_in[3];
    float* out        = (float*)d_out;

    cudaFuncSetAttribute(z_gemm_mma,
                         cudaFuncAttributeMaxDynamicSharedMemorySize, GEMM_SMEM);
    cudaFuncSetAttribute(attn_kernel,
                         cudaFuncAttributeMaxDynamicSharedMemorySize, ATTN_SMEM_BYTES);
    cudaFuncSetAttribute(attn_kernel,
                         cudaFuncAttributePreferredSharedMemoryCarveout, 100);

    prep_w2_kernel<<<2, 256>>>(W, bias);
    convert_x_kernel<<<(M_TOTAL * (DIMC / 4)) / 256, 256>>>(x);   // 50176 blocks
    prep_M_kernel<<<dim3(8, 8), 256>>>(W);
    prep_v_kernel<<<(DIMC * DIMC) / 256, 256>>>(W);               // 1024 blocks

    dim3 gemm_grid(1024 / 128, M_TOTAL / 128);                    // 8 x 784
    z_gemm_mma<<<gemm_grid, 256, GEMM_SMEM>>>(bias);

    attn_kernel<<<NWIN, 256, ATTN_SMEM_BYTES>>>(out);
}